// round 12
// baseline (speedup 1.0000x reference)
#include <cuda_runtime.h>
#include <cstdint>
#include <math.h>

#define B_   32
#define N_   4096
#define D_   256
#define S_   8
#define H_   512
#define TOK  (B_*N_)      // 131072
#define EPS  1e-5f
#define SCALE 0.0625f     // 256^-0.5

// ---------------- scratch (device globals) ----------------------------------
__device__ float g_mean[TOK];
__device__ float g_rstd[TOK];
__device__ float g_slots[B_*S_*D_];
__device__ float g_p[B_*S_*D_];      // pg = SCALE * g ∘ (q @ wk)
__device__ float g_S1[B_*S_];
__device__ float g_S2[B_*S_];
__device__ float g_attn[TOK*S_];     // last iter only
__device__ float g_cs[B_*S_];
__device__ float g_t1[B_*S_];
__device__ float g_U[B_*S_*D_];
__device__ float g_wkgT[D_*D_];      // wkgT[d][j] = ln_in_g[d]*wk[j][d]
__device__ float g_wkb[D_];          // wk @ ln_in_b + bk
__device__ unsigned g_cnt[B_];       // per-batch arrival counter (monotonic per replay)

__device__ __forceinline__ float sigmoidf_(float x) { return 1.f / (1.f + expf(-x)); }

// ---------------- prep (merged): transposed g-scaled wk + wkb ---------------
__global__ void k_prep_all(const float* __restrict__ wk, const float* __restrict__ lng,
                           const float* __restrict__ lnb, const float* __restrict__ bk) {
    if (blockIdx.x < 64) {
        __shared__ float tile[32][33];
        int bj = blockIdx.x & 7, bd = blockIdx.x >> 3;
        int j0 = bj * 32, d0 = bd * 32;
        int tx = threadIdx.x & 31, ty = threadIdx.x >> 5;
        #pragma unroll
        for (int r = 0; r < 4; r++)
            tile[ty + 8*r][tx] = wk[(size_t)(j0 + ty + 8*r) * 256 + d0 + tx];
        __syncthreads();
        #pragma unroll
        for (int r = 0; r < 4; r++) {
            int d = d0 + ty + 8*r;
            g_wkgT[(size_t)d * 256 + j0 + tx] = lng[d] * tile[tx][ty + 8*r];
        }
    } else {
        int j = threadIdx.x;
        const float* wr = wk + (size_t)j * 256;
        float acc = bk[j];
        #pragma unroll 4
        for (int e = 0; e < 256; e += 4) {
            float4 w4 = *(const float4*)&wr[e];
            float4 b4 = *(const float4*)&lnb[e];
            acc += w4.x*b4.x + w4.y*b4.y + w4.z*b4.z + w4.w*b4.w;
        }
        g_wkb[j] = acc;
    }
}

// ---------------- K1: per-token mean/rstd ------------------------------------
__global__ void k_meanvar(const float* __restrict__ x) {
    int warp = threadIdx.x >> 5, lane = threadIdx.x & 31;
    int tok = blockIdx.x * 8 + warp;
    const float4* row = (const float4*)(x + (size_t)tok * D_);
    float4 a = row[lane*2], b = row[lane*2+1];
    float s = a.x+a.y+a.z+a.w + b.x+b.y+b.z+b.w;
    float q = a.x*a.x+a.y*a.y+a.z*a.z+a.w*a.w + b.x*b.x+b.y*b.y+b.z*b.z+b.w*b.w;
    #pragma unroll
    for (int o = 16; o; o >>= 1) {
        s += __shfl_xor_sync(0xffffffffu, s, o);
        q += __shfl_xor_sync(0xffffffffu, q, o);
    }
    if (lane == 0) {
        float m = s * (1.f/256.f);
        g_mean[tok] = m;
        g_rstd[tok] = rsqrtf(q * (1.f/256.f) - m*m + EPS);
    }
}

// ---------------- K4: qproj (iteration 0 only: init slots + pg/S1/S2) -------
__global__ void __launch_bounds__(256) k_qproj3(
    const float* __restrict__ g, const float* __restrict__ bln,
    const float* __restrict__ wq, const float* __restrict__ bq,
    const float* __restrict__ noise, const float* __restrict__ mu,
    const float* __restrict__ sigma_raw)
{
    __shared__ __align__(16) float sa[8][256];
    __shared__ __align__(16) float sq[8][256];
    __shared__ float sm[8], sr[8];
    __shared__ float red1[8][8], red2[8][8];
    int b = blockIdx.x, t = threadIdx.x;
    int w = t >> 5, lane = t & 31;

    float sr_ = sigma_raw[t];
    float sp = (sr_ > 20.f) ? sr_ : log1pf(expf(sr_));
    float muv = mu[t];
    #pragma unroll
    for (int s = 0; s < 8; s++) {
        float v = muv + sp * noise[(b*8+s)*256 + t];
        sa[s][t] = v;
        g_slots[(b*8+s)*256 + t] = v;
        g_U[(b*8+s)*256 + t] = 0.f;
    }
    if (t < 8) { g_cs[b*8 + t] = 0.f; g_t1[b*8 + t] = 0.f; }
    if (t == 0) g_cnt[b] = 0u;
    __syncthreads();

    {
        float s1 = 0.f, s2 = 0.f;
        #pragma unroll
        for (int e = 0; e < 8; e++) {
            float v = sa[w][lane + e*32];
            s1 += v; s2 += v*v;
        }
        #pragma unroll
        for (int o = 16; o; o >>= 1) {
            s1 += __shfl_xor_sync(0xffffffffu, s1, o);
            s2 += __shfl_xor_sync(0xffffffffu, s2, o);
        }
        if (lane == 0) {
            float m = s1 * (1.f/256.f);
            sm[w] = m;
            sr[w] = rsqrtf(s2 * (1.f/256.f) - m*m + EPS);
        }
    }
    __syncthreads();
    float gt = g[t], bt = bln[t];
    #pragma unroll
    for (int s = 0; s < 8; s++)
        sa[s][t] = (sa[s][t] - sm[s]) * sr[s] * gt + bt;
    __syncthreads();

    {
        float acc[8] = {0,0,0,0,0,0,0,0};
        const float* wr = wq + (size_t)t * 256;
        #pragma unroll 2
        for (int e = 0; e < 256; e += 4) {
            float4 w4 = *(const float4*)&wr[e];
            #pragma unroll
            for (int s = 0; s < 8; s++) {
                float4 a4 = *(const float4*)&sa[s][e];
                acc[s] += w4.x*a4.x + w4.y*a4.y + w4.z*a4.z + w4.w*a4.w;
            }
        }
        float bqt = bq[t];
        #pragma unroll
        for (int s = 0; s < 8; s++) sq[s][t] = acc[s] + bqt;
    }
    __syncthreads();

    float pgv[8] = {0,0,0,0,0,0,0,0};
    {
        const float* wr = g_wkgT + (size_t)t * 256;
        #pragma unroll 2
        for (int e = 0; e < 256; e += 4) {
            float4 w4 = *(const float4*)&wr[e];
            #pragma unroll
            for (int s = 0; s < 8; s++) {
                float4 q4 = *(const float4*)&sq[s][e];
                pgv[s] += w4.x*q4.x + w4.y*q4.y + w4.z*q4.z + w4.w*q4.w;
            }
        }
    }
    float wkbt = g_wkb[t];
    float p2[8];
    #pragma unroll
    for (int s = 0; s < 8; s++) {
        pgv[s] *= SCALE;
        g_p[(b*8+s)*256 + t] = pgv[s];
        p2[s] = sq[s][t] * wkbt;
    }
    #pragma unroll
    for (int s = 0; s < 8; s++) {
        float v1 = pgv[s], v2 = p2[s];
        #pragma unroll
        for (int o = 16; o; o >>= 1) {
            v1 += __shfl_xor_sync(0xffffffffu, v1, o);
            v2 += __shfl_xor_sync(0xffffffffu, v2, o);
        }
        if (lane == 0) { red1[s][w] = v1; red2[s][w] = v2; }
    }
    __syncthreads();
    if (t < 8) {
        float a1 = 0.f, a2 = 0.f;
        #pragma unroll
        for (int i = 0; i < 8; i++) { a1 += red1[t][i]; a2 += red2[t][i]; }
        g_S1[b*8 + t] = a1;
        g_S2[b*8 + t] = a2 * SCALE;
    }
}

// ---------------- K5: fused attn + last-CTA gru/qproj tail -------------------
// grid (32 chunks, 32 batches), 128 tokens/CTA
__global__ void __launch_bounds__(256, 2) k_attn6(
    const float* __restrict__ x, int it, int store_attn,
    const float* __restrict__ lng_in, const float* __restrict__ lnb_in,
    const float* __restrict__ wv,   const float* __restrict__ bv,
    const float* __restrict__ w_ih, const float* __restrict__ w_hh,
    const float* __restrict__ b_ih, const float* __restrict__ b_hh,
    const float* __restrict__ lng,  const float* __restrict__ lnb,
    const float* __restrict__ w1,   const float* __restrict__ b1,
    const float* __restrict__ w2,   const float* __restrict__ b2,
    const float* __restrict__ lsg,  const float* __restrict__ lsb,
    const float* __restrict__ wq,   const float* __restrict__ bq,
    float* __restrict__ out_slots)
{
    __shared__ __align__(16) float sA[32][8];
    __shared__ unsigned s_v;
    // gru tail smem
    __shared__ __align__(16) float szn[2][256];
    __shared__ __align__(16) float su[2][256];
    __shared__ __align__(16) float sh[2][256];
    __shared__ __align__(16) float sa2[2][256];
    __shared__ __align__(16) float sh1[2][512];
    __shared__ float smn[2], srr[2];
    __shared__ float red1[2][8], red2[2][8];

    int b = blockIdx.y, chunk = blockIdx.x;
    int t = threadIdx.x;
    int wid = t >> 5, lane = t & 31;
    int slot = (lane >> 2) & 7;

    float pg[8][8];
    {
        const float* pb = g_p + b*S_*D_;
        #pragma unroll
        for (int s = 0; s < 8; s++) {
            float4 a = *(const float4*)&pb[s*256 + lane*8];
            float4 c = *(const float4*)&pb[s*256 + lane*8 + 4];
            pg[s][0]=a.x; pg[s][1]=a.y; pg[s][2]=a.z; pg[s][3]=a.w;
            pg[s][4]=c.x; pg[s][5]=c.y; pg[s][6]=c.z; pg[s][7]=c.w;
        }
    }
    float S1l = g_S1[b*8 + slot];
    float S2l = g_S2[b*8 + slot];

    float u[8]  = {0,0,0,0,0,0,0,0};
    float csA = 0.f, t1A = 0.f;
    int base_tok = b*N_ + chunk*128;

    for (int sub = 0; sub < 4; sub++) {
        int sub0 = sub * 32;
        int n0 = base_tok + sub0 + wid*4;
        const float* xr0 = x + (size_t)n0*256 + lane*8;
        float4 xa = *(const float4*)xr0;
        float4 xb = *(const float4*)(xr0 + 4);
        #pragma unroll
        for (int i = 0; i < 4; i++) {
            int loc = sub0 + wid*4 + i;
            int n = base_tok + loc;
            float4 cxa = xa, cxb = xb;
            if (i < 3) {
                const float* xr = x + (size_t)(n+1)*256 + lane*8;
                xa = *(const float4*)xr;
                xb = *(const float4*)(xr + 4);
            }
            float dt[8];
            #pragma unroll
            for (int s = 0; s < 8; s++) {
                dt[s] = cxa.x*pg[s][0] + cxa.y*pg[s][1] + cxa.z*pg[s][2] + cxa.w*pg[s][3]
                      + cxb.x*pg[s][4] + cxb.y*pg[s][5] + cxb.z*pg[s][6] + cxb.w*pg[s][7];
            }
            float e0, e1, e2, e3;
            {
                float r0 = __shfl_xor_sync(0xffffffffu, dt[0], 16);
                float r1 = __shfl_xor_sync(0xffffffffu, dt[1], 16);
                float r2 = __shfl_xor_sync(0xffffffffu, dt[2], 16);
                float r3 = __shfl_xor_sync(0xffffffffu, dt[3], 16);
                float r4 = __shfl_xor_sync(0xffffffffu, dt[4], 16);
                float r5 = __shfl_xor_sync(0xffffffffu, dt[5], 16);
                float r6 = __shfl_xor_sync(0xffffffffu, dt[6], 16);
                float r7 = __shfl_xor_sync(0xffffffffu, dt[7], 16);
                bool hi = (lane & 16) != 0;
                e0 = hi ? (dt[4]+r4) : (dt[0]+r0);
                e1 = hi ? (dt[5]+r5) : (dt[1]+r1);
                e2 = hi ? (dt[6]+r6) : (dt[2]+r2);
                e3 = hi ? (dt[7]+r7) : (dt[3]+r3);
            }
            float f0, f1;
            {
                float r0 = __shfl_xor_sync(0xffffffffu, e0, 8);
                float r1 = __shfl_xor_sync(0xffffffffu, e1, 8);
                float r2 = __shfl_xor_sync(0xffffffffu, e2, 8);
                float r3 = __shfl_xor_sync(0xffffffffu, e3, 8);
                bool hi = (lane & 8) != 0;
                f0 = hi ? (e2+r2) : (e0+r0);
                f1 = hi ? (e3+r3) : (e1+r1);
            }
            float v;
            {
                float r0 = __shfl_xor_sync(0xffffffffu, f0, 4);
                float r1 = __shfl_xor_sync(0xffffffffu, f1, 4);
                bool hi = (lane & 4) != 0;
                v = hi ? (f1+r1) : (f0+r0);
            }
            v += __shfl_xor_sync(0xffffffffu, v, 2);
            v += __shfl_xor_sync(0xffffffffu, v, 1);

            float r = g_rstd[n], m = g_mean[n];
            float rm = r * m;
            float lg = r*v - rm*S1l + S2l;
            float e = expf(lg);
            float sum = e;
            sum += __shfl_xor_sync(0xffffffffu, sum, 4);
            sum += __shfl_xor_sync(0xffffffffu, sum, 8);
            sum += __shfl_xor_sync(0xffffffffu, sum, 16);
            float a = e / sum + 1e-8f;
            float ar = a * r;
            csA += a;
            t1A += a * rm;
            if ((lane & 3) == 0) {
                sA[loc - sub0][slot] = ar;
                if (store_attn) g_attn[(size_t)n*8 + slot] = a;
            }
        }
        __syncthreads();
        const float* xcol = x + (size_t)(base_tok + sub0)*256 + t;
        #pragma unroll 8
        for (int i = 0; i < 32; i++) {
            float xv = xcol[(size_t)i*256];
            float4 p0 = *(const float4*)&sA[i][0];
            float4 p1 = *(const float4*)&sA[i][4];
            u[0] += p0.x*xv; u[1] += p0.y*xv; u[2] += p0.z*xv; u[3] += p0.w*xv;
            u[4] += p1.x*xv; u[5] += p1.y*xv; u[6] += p1.z*xv; u[7] += p1.w*xv;
        }
        __syncthreads();
    }

    #pragma unroll
    for (int s = 0; s < 8; s++)
        atomicAdd(&g_U[(b*8+s)*256 + t], u[s]);
    if ((lane & 3) == 0) {
        atomicAdd(&g_cs[b*8 + slot], csA);
        atomicAdd(&g_t1[b*8 + slot], t1A);
    }

    // ================= last-4-CTAs-per-batch gru/qproj tail ==================
    __threadfence();
    __syncthreads();
    if (t == 0) s_v = atomicAdd(&g_cnt[b], 1u);
    __syncthreads();
    unsigned v = s_v - 32u * (unsigned)it;     // arrival index 0..31
    if (v < 28u) return;
    int pair = (int)v - 28;                    // slot-pair 0..3
    unsigned target = 32u * (unsigned)(it + 1);
    if (v < 31u) {
        if (t == 0) {
            while (*(volatile unsigned*)&g_cnt[b] < target) { }
        }
        __syncthreads();
    }
    __threadfence();

    int row0 = b*8 + pair*2;
    #pragma unroll
    for (int sl = 0; sl < 2; sl++) {
        int row = row0 + sl;
        float csv = __ldcg(&g_cs[row]), t1v = __ldcg(&g_t1[row]);
        float Ut = __ldcg(&g_U[row*256 + t]);
        szn[sl][t] = lng_in[t] * (Ut - t1v) / csv + lnb_in[t];
        sh[sl][t] = g_slots[row*256 + t];
    }
    __syncthreads();

    {
        float a0 = 0.f, a1 = 0.f;
        const float* wr = wv + (size_t)t * 256;
        #pragma unroll 2
        for (int e = 0; e < 256; e += 4) {
            float4 w4 = *(const float4*)&wr[e];
            float4 z0 = *(const float4*)&szn[0][e];
            float4 z1 = *(const float4*)&szn[1][e];
            a0 += w4.x*z0.x + w4.y*z0.y + w4.z*z0.z + w4.w*z0.w;
            a1 += w4.x*z1.x + w4.y*z1.y + w4.z*z1.z + w4.w*z1.w;
        }
        float bvt = bv[t];
        su[0][t] = a0 + bvt;
        su[1][t] = a1 + bvt;
    }
    __syncthreads();

    float xr[2], xz[2], xn[2], hr[2], hz[2], hn[2];
    #pragma unroll
    for (int sl = 0; sl < 2; sl++) {
        xr[sl] = b_ih[t]; xz[sl] = b_ih[256+t]; xn[sl] = b_ih[512+t];
        hr[sl] = b_hh[t]; hz[sl] = b_hh[256+t]; hn[sl] = b_hh[512+t];
    }
    const float* wir = w_ih + (size_t)t*256;
    const float* wiz = w_ih + (size_t)(256+t)*256;
    const float* win = w_ih + (size_t)(512+t)*256;
    const float* whr = w_hh + (size_t)t*256;
    const float* whz = w_hh + (size_t)(256+t)*256;
    const float* whn = w_hh + (size_t)(512+t)*256;

    #pragma unroll 2
    for (int e = 0; e < 256; e += 4) {
        float4 wr4 = *(const float4*)&wir[e];
        float4 wz4 = *(const float4*)&wiz[e];
        float4 wn4 = *(const float4*)&win[e];
        float4 vr4 = *(const float4*)&whr[e];
        float4 vz4 = *(const float4*)&whz[e];
        float4 vn4 = *(const float4*)&whn[e];
        #pragma unroll
        for (int sl = 0; sl < 2; sl++) {
            float4 u4 = *(const float4*)&su[sl][e];
            float4 h4 = *(const float4*)&sh[sl][e];
            xr[sl] += wr4.x*u4.x + wr4.y*u4.y + wr4.z*u4.z + wr4.w*u4.w;
            xz[sl] += wz4.x*u4.x + wz4.y*u4.y + wz4.z*u4.z + wz4.w*u4.w;
            xn[sl] += wn4.x*u4.x + wn4.y*u4.y + wn4.z*u4.z + wn4.w*u4.w;
            hr[sl] += vr4.x*h4.x + vr4.y*h4.y + vr4.z*h4.z + vr4.w*h4.w;
            hz[sl] += vz4.x*h4.x + vz4.y*h4.y + vz4.z*h4.z + vz4.w*h4.w;
            hn[sl] += vn4.x*h4.x + vn4.y*h4.y + vn4.z*h4.z + vn4.w*h4.w;
        }
    }
    float hnew[2];
    #pragma unroll
    for (int sl = 0; sl < 2; sl++) {
        float r = sigmoidf_(xr[sl] + hr[sl]);
        float z = sigmoidf_(xz[sl] + hz[sl]);
        float nn = tanhf(xn[sl] + r*hn[sl]);
        hnew[sl] = (1.f - z)*nn + z*sh[sl][t];
    }
    __syncthreads();
    su[0][t] = hnew[0]; su[1][t] = hnew[1];
    __syncthreads();
    int w = t >> 5;
    if (w < 2) {
        float s1 = 0.f, s2 = 0.f;
        #pragma unroll
        for (int e = 0; e < 8; e++) {
            float vv = su[w][lane + e*32];
            s1 += vv; s2 += vv*vv;
        }
        #pragma unroll
        for (int o = 16; o; o >>= 1) {
            s1 += __shfl_xor_sync(0xffffffffu, s1, o);
            s2 += __shfl_xor_sync(0xffffffffu, s2, o);
        }
        if (lane == 0) {
            float m = s1 * (1.f/256.f);
            smn[w] = m;
            srr[w] = rsqrtf(s2 * (1.f/256.f) - m*m + EPS);
        }
    }
    __syncthreads();
    float gt = lng[t], bt = lnb[t];
    sa2[0][t] = (hnew[0] - smn[0]) * srr[0] * gt + bt;
    sa2[1][t] = (hnew[1] - smn[1]) * srr[1] * gt + bt;
    __syncthreads();

    float a1g[2] = {b1[t], b1[t]};
    float a2g[2] = {b1[256+t], b1[256+t]};
    const float* w1a = w1 + (size_t)t*256;
    const float* w1b = w1 + (size_t)(256+t)*256;
    #pragma unroll 2
    for (int e = 0; e < 256; e += 4) {
        float4 wa = *(const float4*)&w1a[e];
        float4 wb = *(const float4*)&w1b[e];
        #pragma unroll
        for (int sl = 0; sl < 2; sl++) {
            float4 s4 = *(const float4*)&sa2[sl][e];
            a1g[sl] += wa.x*s4.x + wa.y*s4.y + wa.z*s4.z + wa.w*s4.w;
            a2g[sl] += wb.x*s4.x + wb.y*s4.y + wb.z*s4.z + wb.w*s4.w;
        }
    }
    sh1[0][t] = fmaxf(a1g[0], 0.f); sh1[0][256+t] = fmaxf(a2g[0], 0.f);
    sh1[1][t] = fmaxf(a1g[1], 0.f); sh1[1][256+t] = fmaxf(a2g[1], 0.f);
    __syncthreads();

    float o[2] = {b2[t], b2[t]};
    const float* w2r = w2 + (size_t)t*512;
    #pragma unroll 2
    for (int e = 0; e < 512; e += 4) {
        float4 w4 = *(const float4*)&w2r[e];
        #pragma unroll
        for (int sl = 0; sl < 2; sl++) {
            float4 h4 = *(const float4*)&sh1[sl][e];
            o[sl] += w4.x*h4.x + w4.y*h4.y + w4.z*h4.z + w4.w*h4.w;
        }
    }
    float res[2];
    #pragma unroll
    for (int sl = 0; sl < 2; sl++) {
        res[sl] = hnew[sl] + o[sl];
        g_slots[(row0+sl)*256 + t] = res[sl];
        if (out_slots) out_slots[(row0+sl)*256 + t] = res[sl];
    }

    if (it >= 2) return;

    // ---- fused qproj for next iteration (2 slots) ----
    __syncthreads();
    sh[0][t] = res[0]; sh[1][t] = res[1];
    g_U[(row0+0)*256 + t] = 0.f;
    g_U[(row0+1)*256 + t] = 0.f;
    if (t < 2) { g_cs[row0 + t] = 0.f; g_t1[row0 + t] = 0.f; }
    __syncthreads();
    if (w < 2) {
        float s1 = 0.f, s2 = 0.f;
        #pragma unroll
        for (int e = 0; e < 8; e++) {
            float vv = sh[w][lane + e*32];
            s1 += vv; s2 += vv*vv;
        }
        #pragma unroll
        for (int oo = 16; oo; oo >>= 1) {
            s1 += __shfl_xor_sync(0xffffffffu, s1, oo);
            s2 += __shfl_xor_sync(0xffffffffu, s2, oo);
        }
        if (lane == 0) {
            float m = s1 * (1.f/256.f);
            smn[w] = m;
            srr[w] = rsqrtf(s2 * (1.f/256.f) - m*m + EPS);
        }
    }
    __syncthreads();
    float gst = lsg[t], bst = lsb[t];
    sa2[0][t] = (res[0] - smn[0]) * srr[0] * gst + bst;
    sa2[1][t] = (res[1] - smn[1]) * srr[1] * gst + bst;
    __syncthreads();

    {
        float q0 = 0.f, q1 = 0.f;
        const float* wr = wq + (size_t)t * 256;
        #pragma unroll 2
        for (int e = 0; e < 256; e += 4) {
            float4 w4 = *(const float4*)&wr[e];
            float4 s0 = *(const float4*)&sa2[0][e];
            float4 s1v = *(const float4*)&sa2[1][e];
            q0 += w4.x*s0.x + w4.y*s0.y + w4.z*s0.z + w4.w*s0.w;
            q1 += w4.x*s1v.x + w4.y*s1v.y + w4.z*s1v.z + w4.w*s1v.w;
        }
        float bqt = bq[t];
        szn[0][t] = q0 + bqt;
        szn[1][t] = q1 + bqt;
    }
    __syncthreads();

    float pg0 = 0.f, pg1 = 0.f;
    {
        const float* wr = g_wkgT + (size_t)t * 256;
        #pragma unroll 2
        for (int e = 0; e < 256; e += 4) {
            float4 w4 = *(const float4*)&wr[e];
            float4 q0 = *(const float4*)&szn[0][e];
            float4 q1 = *(const float4*)&szn[1][e];
            pg0 += w4.x*q0.x + w4.y*q0.y + w4.z*q0.z + w4.w*q0.w;
            pg1 += w4.x*q1.x + w4.y*q1.y + w4.z*q1.z + w4.w*q1.w;
        }
    }
    pg0 *= SCALE; pg1 *= SCALE;
    g_p[(row0+0)*256 + t] = pg0;
    g_p[(row0+1)*256 + t] = pg1;
    float wkbt = g_wkb[t];
    float p20 = szn[0][t] * wkbt;
    float p21 = szn[1][t] * wkbt;
    {
        float v0 = pg0, v1 = pg1, v2 = p20, v3 = p21;
        #pragma unroll
        for (int oo = 16; oo; oo >>= 1) {
            v0 += __shfl_xor_sync(0xffffffffu, v0, oo);
            v1 += __shfl_xor_sync(0xffffffffu, v1, oo);
            v2 += __shfl_xor_sync(0xffffffffu, v2, oo);
            v3 += __shfl_xor_sync(0xffffffffu, v3, oo);
        }
        if (lane == 0) {
            red1[0][wid] = v0; red1[1][wid] = v1;
            red2[0][wid] = v2; red2[1][wid] = v3;
        }
    }
    __syncthreads();
    if (t < 2) {
        float a1s = 0.f, a2s = 0.f;
        #pragma unroll
        for (int i = 0; i < 8; i++) { a1s += red1[t][i]; a2s += red2[t][i]; }
        g_S1[row0 + t] = a1s;
        g_S2[row0 + t] = a2s * SCALE;
    }
}

// ---------------- K8: final attn normalize to d_out --------------------------
__global__ void k_attn_out(float* __restrict__ dst) {
    int i = blockIdx.x*blockDim.x + threadIdx.x;
    if (i < TOK*S_) {
        int s = i & 7;
        int b = i >> 15;
        dst[i] = g_attn[i] / g_cs[b*8 + s];
    }
}

// ---------------- host --------------------------------------------------------
extern "C" void kernel_launch(void* const* d_in, const int* in_sizes, int n_in,
                              void* d_out, int out_size) {
    const float* inputs     = (const float*)d_in[0];
    const float* init_noise = (const float*)d_in[1];
    const float* mu         = (const float*)d_in[2];
    const float* sigma_raw  = (const float*)d_in[3];
    const float* ln_in_g    = (const float*)d_in[4];
    const float* ln_in_b    = (const float*)d_in[5];
    const float* ln_s_g     = (const float*)d_in[6];
    const float* ln_s_b     = (const float*)d_in[7];
    const float* ln_m_g     = (const float*)d_in[8];
    const float* ln_m_b     = (const float*)d_in[9];
    const float* wq         = (const float*)d_in[10];
    const float* bq         = (const float*)d_in[11];
    const float* wk         = (const float*)d_in[12];
    const float* bk         = (const float*)d_in[13];
    const float* wv         = (const float*)d_in[14];
    const float* bv         = (const float*)d_in[15];
    const float* w_ih       = (const float*)d_in[16];
    const float* w_hh       = (const float*)d_in[17];
    const float* b_ih       = (const float*)d_in[18];
    const float* b_hh       = (const float*)d_in[19];
    const float* w1         = (const float*)d_in[20];
    const float* b1         = (const float*)d_in[21];
    const float* w2         = (const float*)d_in[22];
    const float* b2         = (const float*)d_in[23];
    float* out = (float*)d_out;

    k_prep_all<<<65, 256>>>(wk, ln_in_g, ln_in_b, bk);
    k_meanvar<<<TOK/8, 256>>>(inputs);
    k_qproj3<<<B_, 256>>>(ln_s_g, ln_s_b, wq, bq, init_noise, mu, sigma_raw);

    for (int it = 0; it < 3; ++it) {
        bool last = (it == 2);
        k_attn6<<<dim3(32, B_), 256>>>(inputs, it, last ? 1 : 0,
                                       ln_in_g, ln_in_b, wv, bv,
                                       w_ih, w_hh, b_ih, b_hh, ln_m_g, ln_m_b,
                                       w1, b1, w2, b2,
                                       ln_s_g, ln_s_b, wq, bq,
                                       last ? out : nullptr);
    }
    k_attn_out<<<(TOK*S_ + 255)/256, 256>>>(out + B_*S_*D_);
}

// round 13
// speedup vs baseline: 1.4146x; 1.4146x over previous
#include <cuda_runtime.h>
#include <cstdint>
#include <math.h>

#define B_   32
#define N_   4096
#define D_   256
#define S_   8
#define H_   512
#define TOK  (B_*N_)      // 131072
#define EPS  1e-5f
#define SCALE 0.0625f     // 256^-0.5

// ---------------- scratch (device globals) ----------------------------------
__device__ float g_mean[TOK];
__device__ float g_rstd[TOK];
__device__ float g_slots[B_*S_*D_];
__device__ float g_p[B_*S_*D_];      // pg = SCALE * g ∘ (q @ wk)
__device__ float g_S1[B_*S_];
__device__ float g_S2[B_*S_];
__device__ float g_attn[TOK*S_];     // last iter only
__device__ float g_cs[B_*S_];
__device__ float g_t1[B_*S_];
__device__ float g_U[B_*S_*D_];
__device__ float g_wkgT[D_*D_];      // wkgT[d][j] = ln_in_g[d]*wk[j][d]
__device__ float g_wkb[D_];          // wk @ ln_in_b + bk

__device__ __forceinline__ float sigmoidf_(float x) { return 1.f / (1.f + expf(-x)); }

// ---------------- prep (merged): transposed g-scaled wk + wkb ---------------
__global__ void k_prep_all(const float* __restrict__ wk, const float* __restrict__ lng,
                           const float* __restrict__ lnb, const float* __restrict__ bk) {
    if (blockIdx.x < 64) {
        __shared__ float tile[32][33];
        int bj = blockIdx.x & 7, bd = blockIdx.x >> 3;
        int j0 = bj * 32, d0 = bd * 32;
        int tx = threadIdx.x & 31, ty = threadIdx.x >> 5;
        #pragma unroll
        for (int r = 0; r < 4; r++)
            tile[ty + 8*r][tx] = wk[(size_t)(j0 + ty + 8*r) * 256 + d0 + tx];
        __syncthreads();
        #pragma unroll
        for (int r = 0; r < 4; r++) {
            int d = d0 + ty + 8*r;
            g_wkgT[(size_t)d * 256 + j0 + tx] = lng[d] * tile[tx][ty + 8*r];
        }
    } else {
        int j = threadIdx.x;
        const float* wr = wk + (size_t)j * 256;
        float acc = bk[j];
        #pragma unroll 4
        for (int e = 0; e < 256; e += 4) {
            float4 w4 = *(const float4*)&wr[e];
            float4 b4 = *(const float4*)&lnb[e];
            acc += w4.x*b4.x + w4.y*b4.y + w4.z*b4.z + w4.w*b4.w;
        }
        g_wkb[j] = acc;
    }
}

// ---------------- K1: per-token mean/rstd ------------------------------------
__global__ void k_meanvar(const float* __restrict__ x) {
    int warp = threadIdx.x >> 5, lane = threadIdx.x & 31;
    int tok = blockIdx.x * 8 + warp;
    const float4* row = (const float4*)(x + (size_t)tok * D_);
    float4 a = row[lane*2], b = row[lane*2+1];
    float s = a.x+a.y+a.z+a.w + b.x+b.y+b.z+b.w;
    float q = a.x*a.x+a.y*a.y+a.z*a.z+a.w*a.w + b.x*b.x+b.y*b.y+b.z*b.z+b.w*b.w;
    #pragma unroll
    for (int o = 16; o; o >>= 1) {
        s += __shfl_xor_sync(0xffffffffu, s, o);
        q += __shfl_xor_sync(0xffffffffu, q, o);
    }
    if (lane == 0) {
        float m = s * (1.f/256.f);
        g_mean[tok] = m;
        g_rstd[tok] = rsqrtf(q * (1.f/256.f) - m*m + EPS);
    }
}

// ---------------- K4: qproj (iteration 0 only: init slots + pg/S1/S2) -------
__global__ void __launch_bounds__(256) k_qproj3(
    const float* __restrict__ g, const float* __restrict__ bln,
    const float* __restrict__ wq, const float* __restrict__ bq,
    const float* __restrict__ noise, const float* __restrict__ mu,
    const float* __restrict__ sigma_raw)
{
    __shared__ __align__(16) float sa[8][256];
    __shared__ __align__(16) float sq[8][256];
    __shared__ float sm[8], sr[8];
    __shared__ float red1[8][8], red2[8][8];
    int b = blockIdx.x, t = threadIdx.x;
    int w = t >> 5, lane = t & 31;

    float sr_ = sigma_raw[t];
    float sp = (sr_ > 20.f) ? sr_ : log1pf(expf(sr_));
    float muv = mu[t];
    #pragma unroll
    for (int s = 0; s < 8; s++) {
        float v = muv + sp * noise[(b*8+s)*256 + t];
        sa[s][t] = v;
        g_slots[(b*8+s)*256 + t] = v;
        g_U[(b*8+s)*256 + t] = 0.f;
    }
    if (t < 8) { g_cs[b*8 + t] = 0.f; g_t1[b*8 + t] = 0.f; }
    __syncthreads();

    {
        float s1 = 0.f, s2 = 0.f;
        #pragma unroll
        for (int e = 0; e < 8; e++) {
            float v = sa[w][lane + e*32];
            s1 += v; s2 += v*v;
        }
        #pragma unroll
        for (int o = 16; o; o >>= 1) {
            s1 += __shfl_xor_sync(0xffffffffu, s1, o);
            s2 += __shfl_xor_sync(0xffffffffu, s2, o);
        }
        if (lane == 0) {
            float m = s1 * (1.f/256.f);
            sm[w] = m;
            sr[w] = rsqrtf(s2 * (1.f/256.f) - m*m + EPS);
        }
    }
    __syncthreads();
    float gt = g[t], bt = bln[t];
    #pragma unroll
    for (int s = 0; s < 8; s++)
        sa[s][t] = (sa[s][t] - sm[s]) * sr[s] * gt + bt;
    __syncthreads();

    {
        float acc[8] = {0,0,0,0,0,0,0,0};
        const float* wr = wq + (size_t)t * 256;
        #pragma unroll 2
        for (int e = 0; e < 256; e += 4) {
            float4 w4 = *(const float4*)&wr[e];
            #pragma unroll
            for (int s = 0; s < 8; s++) {
                float4 a4 = *(const float4*)&sa[s][e];
                acc[s] += w4.x*a4.x + w4.y*a4.y + w4.z*a4.z + w4.w*a4.w;
            }
        }
        float bqt = bq[t];
        #pragma unroll
        for (int s = 0; s < 8; s++) sq[s][t] = acc[s] + bqt;
    }
    __syncthreads();

    float pgv[8] = {0,0,0,0,0,0,0,0};
    {
        const float* wr = g_wkgT + (size_t)t * 256;
        #pragma unroll 2
        for (int e = 0; e < 256; e += 4) {
            float4 w4 = *(const float4*)&wr[e];
            #pragma unroll
            for (int s = 0; s < 8; s++) {
                float4 q4 = *(const float4*)&sq[s][e];
                pgv[s] += w4.x*q4.x + w4.y*q4.y + w4.z*q4.z + w4.w*q4.w;
            }
        }
    }
    float wkbt = g_wkb[t];
    float p2[8];
    #pragma unroll
    for (int s = 0; s < 8; s++) {
        pgv[s] *= SCALE;
        g_p[(b*8+s)*256 + t] = pgv[s];
        p2[s] = sq[s][t] * wkbt;
    }
    #pragma unroll
    for (int s = 0; s < 8; s++) {
        float v1 = pgv[s], v2 = p2[s];
        #pragma unroll
        for (int o = 16; o; o >>= 1) {
            v1 += __shfl_xor_sync(0xffffffffu, v1, o);
            v2 += __shfl_xor_sync(0xffffffffu, v2, o);
        }
        if (lane == 0) { red1[s][w] = v1; red2[s][w] = v2; }
    }
    __syncthreads();
    if (t < 8) {
        float a1 = 0.f, a2 = 0.f;
        #pragma unroll
        for (int i = 0; i < 8; i++) { a1 += red1[t][i]; a2 += red2[t][i]; }
        g_S1[b*8 + t] = a1;
        g_S2[b*8 + t] = a2 * SCALE;
    }
}

// ---------------- K5: fused attn (register pg, 2-token interleaved) ---------
// grid (32 chunks, 32 batches), 128 tokens/CTA
__global__ void __launch_bounds__(256, 2) k_attn7(const float* __restrict__ x,
                                                  int store_attn) {
    __shared__ __align__(16) float sA[32][8];
    int b = blockIdx.y, chunk = blockIdx.x;
    int t = threadIdx.x;
    int wid = t >> 5, lane = t & 31;
    int slot = (lane >> 2) & 7;

    float pg[8][8];
    {
        const float* pb = g_p + b*S_*D_;
        #pragma unroll
        for (int s = 0; s < 8; s++) {
            float4 a = *(const float4*)&pb[s*256 + lane*8];
            float4 c = *(const float4*)&pb[s*256 + lane*8 + 4];
            pg[s][0]=a.x; pg[s][1]=a.y; pg[s][2]=a.z; pg[s][3]=a.w;
            pg[s][4]=c.x; pg[s][5]=c.y; pg[s][6]=c.z; pg[s][7]=c.w;
        }
    }
    float S1l = g_S1[b*8 + slot];
    float S2l = g_S2[b*8 + slot];

    float u[8]  = {0,0,0,0,0,0,0,0};
    float csA = 0.f, t1A = 0.f;
    int base_tok = b*N_ + chunk*128;

    for (int sub = 0; sub < 4; sub++) {
        int sub0 = sub * 32;
        #pragma unroll
        for (int i = 0; i < 4; i += 2) {
            int locA = sub0 + wid*4 + i;
            int nA = base_tok + locA;
            int nB = nA + 1;
            const float* xrA = x + (size_t)nA*256 + lane*8;
            const float* xrB = x + (size_t)nB*256 + lane*8;
            float4 xaA = *(const float4*)xrA;
            float4 xbA = *(const float4*)(xrA + 4);
            float4 xaB = *(const float4*)xrB;
            float4 xbB = *(const float4*)(xrB + 4);

            float dA[8], dB[8];
            #pragma unroll
            for (int s = 0; s < 8; s++) {
                dA[s] = xaA.x*pg[s][0] + xaA.y*pg[s][1] + xaA.z*pg[s][2] + xaA.w*pg[s][3]
                      + xbA.x*pg[s][4] + xbA.y*pg[s][5] + xbA.z*pg[s][6] + xbA.w*pg[s][7];
                dB[s] = xaB.x*pg[s][0] + xaB.y*pg[s][1] + xaB.z*pg[s][2] + xaB.w*pg[s][3]
                      + xbB.x*pg[s][4] + xbB.y*pg[s][5] + xbB.z*pg[s][6] + xbB.w*pg[s][7];
            }
            // ---- interleaved halving trees (independent chains) ----
            bool h16 = (lane & 16) != 0;
            float eA0, eA1, eA2, eA3, eB0, eB1, eB2, eB3;
            {
                float rA0 = __shfl_xor_sync(0xffffffffu, dA[0], 16);
                float rB0 = __shfl_xor_sync(0xffffffffu, dB[0], 16);
                float rA1 = __shfl_xor_sync(0xffffffffu, dA[1], 16);
                float rB1 = __shfl_xor_sync(0xffffffffu, dB[1], 16);
                float rA2 = __shfl_xor_sync(0xffffffffu, dA[2], 16);
                float rB2 = __shfl_xor_sync(0xffffffffu, dB[2], 16);
                float rA3 = __shfl_xor_sync(0xffffffffu, dA[3], 16);
                float rB3 = __shfl_xor_sync(0xffffffffu, dB[3], 16);
                float rA4 = __shfl_xor_sync(0xffffffffu, dA[4], 16);
                float rB4 = __shfl_xor_sync(0xffffffffu, dB[4], 16);
                float rA5 = __shfl_xor_sync(0xffffffffu, dA[5], 16);
                float rB5 = __shfl_xor_sync(0xffffffffu, dB[5], 16);
                float rA6 = __shfl_xor_sync(0xffffffffu, dA[6], 16);
                float rB6 = __shfl_xor_sync(0xffffffffu, dB[6], 16);
                float rA7 = __shfl_xor_sync(0xffffffffu, dA[7], 16);
                float rB7 = __shfl_xor_sync(0xffffffffu, dB[7], 16);
                eA0 = h16 ? (dA[4]+rA4) : (dA[0]+rA0);
                eA1 = h16 ? (dA[5]+rA5) : (dA[1]+rA1);
                eA2 = h16 ? (dA[6]+rA6) : (dA[2]+rA2);
                eA3 = h16 ? (dA[7]+rA7) : (dA[3]+rA3);
                eB0 = h16 ? (dB[4]+rB4) : (dB[0]+rB0);
                eB1 = h16 ? (dB[5]+rB5) : (dB[1]+rB1);
                eB2 = h16 ? (dB[6]+rB6) : (dB[2]+rB2);
                eB3 = h16 ? (dB[7]+rB7) : (dB[3]+rB3);
            }
            bool h8 = (lane & 8) != 0;
            float fA0, fA1, fB0, fB1;
            {
                float rA0 = __shfl_xor_sync(0xffffffffu, eA0, 8);
                float rB0 = __shfl_xor_sync(0xffffffffu, eB0, 8);
                float rA1 = __shfl_xor_sync(0xffffffffu, eA1, 8);
                float rB1 = __shfl_xor_sync(0xffffffffu, eB1, 8);
                float rA2 = __shfl_xor_sync(0xffffffffu, eA2, 8);
                float rB2 = __shfl_xor_sync(0xffffffffu, eB2, 8);
                float rA3 = __shfl_xor_sync(0xffffffffu, eA3, 8);
                float rB3 = __shfl_xor_sync(0xffffffffu, eB3, 8);
                fA0 = h8 ? (eA2+rA2) : (eA0+rA0);
                fA1 = h8 ? (eA3+rA3) : (eA1+rA1);
                fB0 = h8 ? (eB2+rB2) : (eB0+rB0);
                fB1 = h8 ? (eB3+rB3) : (eB1+rB1);
            }
            bool h4 = (lane & 4) != 0;
            float vA, vB;
            {
                float rA0 = __shfl_xor_sync(0xffffffffu, fA0, 4);
                float rB0 = __shfl_xor_sync(0xffffffffu, fB0, 4);
                float rA1 = __shfl_xor_sync(0xffffffffu, fA1, 4);
                float rB1 = __shfl_xor_sync(0xffffffffu, fB1, 4);
                vA = h4 ? (fA1+rA1) : (fA0+rA0);
                vB = h4 ? (fB1+rB1) : (fB0+rB0);
            }
            vA += __shfl_xor_sync(0xffffffffu, vA, 2);
            vB += __shfl_xor_sync(0xffffffffu, vB, 2);
            vA += __shfl_xor_sync(0xffffffffu, vA, 1);
            vB += __shfl_xor_sync(0xffffffffu, vB, 1);

            float rA = g_rstd[nA], mA = g_mean[nA];
            float rB = g_rstd[nB], mB = g_mean[nB];
            float rmA = rA * mA, rmB = rB * mB;
            float lgA = rA*vA - rmA*S1l + S2l;
            float lgB = rB*vB - rmB*S1l + S2l;
            float eA = expf(lgA);
            float eB = expf(lgB);
            float sumA = eA, sumB = eB;
            sumA += __shfl_xor_sync(0xffffffffu, sumA, 4);
            sumB += __shfl_xor_sync(0xffffffffu, sumB, 4);
            sumA += __shfl_xor_sync(0xffffffffu, sumA, 8);
            sumB += __shfl_xor_sync(0xffffffffu, sumB, 8);
            sumA += __shfl_xor_sync(0xffffffffu, sumA, 16);
            sumB += __shfl_xor_sync(0xffffffffu, sumB, 16);
            float aA = eA / sumA + 1e-8f;
            float aB = eB / sumB + 1e-8f;
            csA += aA + aB;
            t1A += aA * rmA + aB * rmB;
            if ((lane & 3) == 0) {
                sA[locA - sub0][slot]     = aA * rA;
                sA[locA - sub0 + 1][slot] = aB * rB;
                if (store_attn) {
                    g_attn[(size_t)nA*8 + slot] = aA;
                    g_attn[(size_t)nB*8 + slot] = aB;
                }
            }
        }
        __syncthreads();
        const float* xcol = x + (size_t)(base_tok + sub0)*256 + t;
        #pragma unroll 8
        for (int i = 0; i < 32; i++) {
            float xv = xcol[(size_t)i*256];
            float4 p0 = *(const float4*)&sA[i][0];
            float4 p1 = *(const float4*)&sA[i][4];
            u[0] += p0.x*xv; u[1] += p0.y*xv; u[2] += p0.z*xv; u[3] += p0.w*xv;
            u[4] += p1.x*xv; u[5] += p1.y*xv; u[6] += p1.z*xv; u[7] += p1.w*xv;
        }
        __syncthreads();
    }

    #pragma unroll
    for (int s = 0; s < 8; s++)
        atomicAdd(&g_U[(b*8+s)*256 + t], u[s]);
    if ((lane & 3) == 0) {
        atomicAdd(&g_cs[b*8 + slot], csA);
        atomicAdd(&g_t1[b*8 + slot], t1A);
    }
}

// ---------------- K7: GRU + LN + MLP (+ fused next-iter qproj) --------------
__global__ void __launch_bounds__(256) k_gruq(
    const float* __restrict__ lng_in, const float* __restrict__ lnb_in,
    const float* __restrict__ wv,   const float* __restrict__ bv,
    const float* __restrict__ w_ih, const float* __restrict__ w_hh,
    const float* __restrict__ b_ih, const float* __restrict__ b_hh,
    const float* __restrict__ lng,  const float* __restrict__ lnb,
    const float* __restrict__ w1,   const float* __restrict__ b1,
    const float* __restrict__ w2,   const float* __restrict__ b2,
    const float* __restrict__ lsg,  const float* __restrict__ lsb,
    const float* __restrict__ wq,   const float* __restrict__ bq,
    int do_qproj, float* __restrict__ out_slots)
{
    __shared__ __align__(16) float szn[2][256];
    __shared__ __align__(16) float su[2][256];
    __shared__ __align__(16) float sh[2][256];
    __shared__ __align__(16) float sa[2][256];
    __shared__ __align__(16) float sh1[2][512];
    __shared__ float sm[2], sr2[2];
    __shared__ float red1[2][8], red2[2][8];

    int b = blockIdx.x >> 2;
    int p = blockIdx.x & 3;
    int row0 = b*8 + p*2;
    int t = threadIdx.x;

    #pragma unroll
    for (int sl = 0; sl < 2; sl++) {
        int row = row0 + sl;
        float csv = g_cs[row], t1v = g_t1[row];
        float Ut = g_U[row*256 + t];
        szn[sl][t] = lng_in[t] * (Ut - t1v) / csv + lnb_in[t];
        sh[sl][t] = g_slots[row*256 + t];
    }
    __syncthreads();

    {
        float a0 = 0.f, a1 = 0.f;
        const float* wr = wv + (size_t)t * 256;
        #pragma unroll 2
        for (int e = 0; e < 256; e += 4) {
            float4 w4 = *(const float4*)&wr[e];
            float4 z0 = *(const float4*)&szn[0][e];
            float4 z1 = *(const float4*)&szn[1][e];
            a0 += w4.x*z0.x + w4.y*z0.y + w4.z*z0.z + w4.w*z0.w;
            a1 += w4.x*z1.x + w4.y*z1.y + w4.z*z1.z + w4.w*z1.w;
        }
        float bvt = bv[t];
        su[0][t] = a0 + bvt;
        su[1][t] = a1 + bvt;
    }
    __syncthreads();

    float xr[2], xz[2], xn[2], hr[2], hz[2], hn[2];
    #pragma unroll
    for (int sl = 0; sl < 2; sl++) {
        xr[sl] = b_ih[t]; xz[sl] = b_ih[256+t]; xn[sl] = b_ih[512+t];
        hr[sl] = b_hh[t]; hz[sl] = b_hh[256+t]; hn[sl] = b_hh[512+t];
    }
    const float* wir = w_ih + (size_t)t*256;
    const float* wiz = w_ih + (size_t)(256+t)*256;
    const float* win = w_ih + (size_t)(512+t)*256;
    const float* whr = w_hh + (size_t)t*256;
    const float* whz = w_hh + (size_t)(256+t)*256;
    const float* whn = w_hh + (size_t)(512+t)*256;

    #pragma unroll 2
    for (int e = 0; e < 256; e += 4) {
        float4 wr4 = *(const float4*)&wir[e];
        float4 wz4 = *(const float4*)&wiz[e];
        float4 wn4 = *(const float4*)&win[e];
        float4 vr4 = *(const float4*)&whr[e];
        float4 vz4 = *(const float4*)&whz[e];
        float4 vn4 = *(const float4*)&whn[e];
        #pragma unroll
        for (int sl = 0; sl < 2; sl++) {
            float4 u4 = *(const float4*)&su[sl][e];
            float4 h4 = *(const float4*)&sh[sl][e];
            xr[sl] += wr4.x*u4.x + wr4.y*u4.y + wr4.z*u4.z + wr4.w*u4.w;
            xz[sl] += wz4.x*u4.x + wz4.y*u4.y + wz4.z*u4.z + wz4.w*u4.w;
            xn[sl] += wn4.x*u4.x + wn4.y*u4.y + wn4.z*u4.z + wn4.w*u4.w;
            hr[sl] += vr4.x*h4.x + vr4.y*h4.y + vr4.z*h4.z + vr4.w*h4.w;
            hz[sl] += vz4.x*h4.x + vz4.y*h4.y + vz4.z*h4.z + vz4.w*h4.w;
            hn[sl] += vn4.x*h4.x + vn4.y*h4.y + vn4.z*h4.z + vn4.w*h4.w;
        }
    }
    float hnew[2];
    #pragma unroll
    for (int sl = 0; sl < 2; sl++) {
        float r = sigmoidf_(xr[sl] + hr[sl]);
        float z = sigmoidf_(xz[sl] + hz[sl]);
        float nn = tanhf(xn[sl] + r*hn[sl]);
        hnew[sl] = (1.f - z)*nn + z*sh[sl][t];
    }
    __syncthreads();
    su[0][t] = hnew[0]; su[1][t] = hnew[1];
    __syncthreads();
    int w = t >> 5, lane = t & 31;
    if (w < 2) {
        float s1 = 0.f, s2 = 0.f;
        #pragma unroll
        for (int e = 0; e < 8; e++) {
            float v = su[w][lane + e*32];
            s1 += v; s2 += v*v;
        }
        #pragma unroll
        for (int o = 16; o; o >>= 1) {
            s1 += __shfl_xor_sync(0xffffffffu, s1, o);
            s2 += __shfl_xor_sync(0xffffffffu, s2, o);
        }
        if (lane == 0) {
            float m = s1 * (1.f/256.f);
            sm[w] = m;
            sr2[w] = rsqrtf(s2 * (1.f/256.f) - m*m + EPS);
        }
    }
    __syncthreads();
    float gt = lng[t], bt = lnb[t];
    sa[0][t] = (hnew[0] - sm[0]) * sr2[0] * gt + bt;
    sa[1][t] = (hnew[1] - sm[1]) * sr2[1] * gt + bt;
    __syncthreads();

    float a1[2] = {b1[t], b1[t]};
    float a2[2] = {b1[256+t], b1[256+t]};
    const float* w1a = w1 + (size_t)t*256;
    const float* w1b = w1 + (size_t)(256+t)*256;
    #pragma unroll 2
    for (int e = 0; e < 256; e += 4) {
        float4 wa = *(const float4*)&w1a[e];
        float4 wb = *(const float4*)&w1b[e];
        #pragma unroll
        for (int sl = 0; sl < 2; sl++) {
            float4 s4 = *(const float4*)&sa[sl][e];
            a1[sl] += wa.x*s4.x + wa.y*s4.y + wa.z*s4.z + wa.w*s4.w;
            a2[sl] += wb.x*s4.x + wb.y*s4.y + wb.z*s4.z + wb.w*s4.w;
        }
    }
    sh1[0][t] = fmaxf(a1[0], 0.f); sh1[0][256+t] = fmaxf(a2[0], 0.f);
    sh1[1][t] = fmaxf(a1[1], 0.f); sh1[1][256+t] = fmaxf(a2[1], 0.f);
    __syncthreads();

    float o[2] = {b2[t], b2[t]};
    const float* w2r = w2 + (size_t)t*512;
    #pragma unroll 2
    for (int e = 0; e < 512; e += 4) {
        float4 w4 = *(const float4*)&w2r[e];
        #pragma unroll
        for (int sl = 0; sl < 2; sl++) {
            float4 h4 = *(const float4*)&sh1[sl][e];
            o[sl] += w4.x*h4.x + w4.y*h4.y + w4.z*h4.z + w4.w*h4.w;
        }
    }
    float res[2];
    #pragma unroll
    for (int sl = 0; sl < 2; sl++) {
        res[sl] = hnew[sl] + o[sl];
        g_slots[(row0+sl)*256 + t] = res[sl];
        if (out_slots) out_slots[(row0+sl)*256 + t] = res[sl];
    }

    if (!do_qproj) return;

    // ======== fused qproj for next iteration (2 slots) ========
    __syncthreads();
    sh[0][t] = res[0]; sh[1][t] = res[1];
    g_U[(row0+0)*256 + t] = 0.f;
    g_U[(row0+1)*256 + t] = 0.f;
    if (t < 2) { g_cs[row0 + t] = 0.f; g_t1[row0 + t] = 0.f; }
    __syncthreads();
    if (w < 2) {
        float s1 = 0.f, s2 = 0.f;
        #pragma unroll
        for (int e = 0; e < 8; e++) {
            float v = sh[w][lane + e*32];
            s1 += v; s2 += v*v;
        }
        #pragma unroll
        for (int oo = 16; oo; oo >>= 1) {
            s1 += __shfl_xor_sync(0xffffffffu, s1, oo);
            s2 += __shfl_xor_sync(0xffffffffu, s2, oo);
        }
        if (lane == 0) {
            float m = s1 * (1.f/256.f);
            sm[w] = m;
            sr2[w] = rsqrtf(s2 * (1.f/256.f) - m*m + EPS);
        }
    }
    __syncthreads();
    float gst = lsg[t], bst = lsb[t];
    sa[0][t] = (res[0] - sm[0]) * sr2[0] * gst + bst;
    sa[1][t] = (res[1] - sm[1]) * sr2[1] * gst + bst;
    __syncthreads();

    {
        float q0 = 0.f, q1 = 0.f;
        const float* wr = wq + (size_t)t * 256;
        #pragma unroll 2
        for (int e = 0; e < 256; e += 4) {
            float4 w4 = *(const float4*)&wr[e];
            float4 s0 = *(const float4*)&sa[0][e];
            float4 s1v = *(const float4*)&sa[1][e];
            q0 += w4.x*s0.x + w4.y*s0.y + w4.z*s0.z + w4.w*s0.w;
            q1 += w4.x*s1v.x + w4.y*s1v.y + w4.z*s1v.z + w4.w*s1v.w;
        }
        float bqt = bq[t];
        szn[0][t] = q0 + bqt;
        szn[1][t] = q1 + bqt;
    }
    __syncthreads();

    float pg0 = 0.f, pg1 = 0.f;
    {
        const float* wr = g_wkgT + (size_t)t * 256;
        #pragma unroll 2
        for (int e = 0; e < 256; e += 4) {
            float4 w4 = *(const float4*)&wr[e];
            float4 q0 = *(const float4*)&szn[0][e];
            float4 q1 = *(const float4*)&szn[1][e];
            pg0 += w4.x*q0.x + w4.y*q0.y + w4.z*q0.z + w4.w*q0.w;
            pg1 += w4.x*q1.x + w4.y*q1.y + w4.z*q1.z + w4.w*q1.w;
        }
    }
    pg0 *= SCALE; pg1 *= SCALE;
    g_p[(row0+0)*256 + t] = pg0;
    g_p[(row0+1)*256 + t] = pg1;
    float wkbt = g_wkb[t];
    float p20 = szn[0][t] * wkbt;
    float p21 = szn[1][t] * wkbt;
    {
        float v0 = pg0, v1 = pg1, v2 = p20, v3 = p21;
        int wid = t >> 5;
        #pragma unroll
        for (int oo = 16; oo; oo >>= 1) {
            v0 += __shfl_xor_sync(0xffffffffu, v0, oo);
            v1 += __shfl_xor_sync(0xffffffffu, v1, oo);
            v2 += __shfl_xor_sync(0xffffffffu, v2, oo);
            v3 += __shfl_xor_sync(0xffffffffu, v3, oo);
        }
        if (lane == 0) {
            red1[0][wid] = v0; red1[1][wid] = v1;
            red2[0][wid] = v2; red2[1][wid] = v3;
        }
    }
    __syncthreads();
    if (t < 2) {
        float a1s = 0.f, a2s = 0.f;
        #pragma unroll
        for (int i = 0; i < 8; i++) { a1s += red1[t][i]; a2s += red2[t][i]; }
        g_S1[row0 + t] = a1s;
        g_S2[row0 + t] = a2s * SCALE;
    }
}

// ---------------- K8: final attn normalize to d_out --------------------------
__global__ void k_attn_out(float* __restrict__ dst) {
    int i = blockIdx.x*blockDim.x + threadIdx.x;
    if (i < TOK*S_) {
        int s = i & 7;
        int b = i >> 15;
        dst[i] = g_attn[i] / g_cs[b*8 + s];
    }
}

// ---------------- host --------------------------------------------------------
extern "C" void kernel_launch(void* const* d_in, const int* in_sizes, int n_in,
                              void* d_out, int out_size) {
    const float* inputs     = (const float*)d_in[0];
    const float* init_noise = (const float*)d_in[1];
    const float* mu         = (const float*)d_in[2];
    const float* sigma_raw  = (const float*)d_in[3];
    const float* ln_in_g    = (const float*)d_in[4];
    const float* ln_in_b    = (const float*)d_in[5];
    const float* ln_s_g     = (const float*)d_in[6];
    const float* ln_s_b     = (const float*)d_in[7];
    const float* ln_m_g     = (const float*)d_in[8];
    const float* ln_m_b     = (const float*)d_in[9];
    const float* wq         = (const float*)d_in[10];
    const float* bq         = (const float*)d_in[11];
    const float* wk         = (const float*)d_in[12];
    const float* bk         = (const float*)d_in[13];
    const float* wv         = (const float*)d_in[14];
    const float* bv         = (const float*)d_in[15];
    const float* w_ih       = (const float*)d_in[16];
    const float* w_hh       = (const float*)d_in[17];
    const float* b_ih       = (const float*)d_in[18];
    const float* b_hh       = (const float*)d_in[19];
    const float* w1         = (const float*)d_in[20];
    const float* b1         = (const float*)d_in[21];
    const float* w2         = (const float*)d_in[22];
    const float* b2         = (const float*)d_in[23];
    float* out = (float*)d_out;

    k_prep_all<<<65, 256>>>(wk, ln_in_g, ln_in_b, bk);
    k_meanvar<<<TOK/8, 256>>>(inputs);
    k_qproj3<<<B_, 256>>>(ln_s_g, ln_s_b, wq, bq, init_noise, mu, sigma_raw);

    for (int it = 0; it < 3; ++it) {
        bool last = (it == 2);
        k_attn7<<<dim3(32, B_), 256>>>(inputs, last ? 1 : 0);
        k_gruq<<<B_*4, 256>>>(ln_in_g, ln_in_b, wv, bv,
                              w_ih, w_hh, b_ih, b_hh, ln_m_g, ln_m_b,
                              w1, b1, w2, b2,
                              ln_s_g, ln_s_b, wq, bq,
                              last ? 0 : 1, last ? out : nullptr);
    }
    k_attn_out<<<(TOK*S_ + 255)/256, 256>>>(out + B_*S_*D_);
}

// round 14
// speedup vs baseline: 1.4272x; 1.0089x over previous
#include <cuda_runtime.h>
#include <cstdint>
#include <math.h>

#define B_   32
#define N_   4096
#define D_   256
#define S_   8
#define H_   512
#define TOK  (B_*N_)      // 131072
#define EPS  1e-5f
#define SCALE 0.0625f     // 256^-0.5

// ---------------- scratch (device globals) ----------------------------------
__device__ float g_mean[TOK];
__device__ float g_rstd[TOK];
__device__ float g_slots[B_*S_*D_];
__device__ float g_p[B_*S_*D_];      // pg = SCALE * g ∘ (q @ wk)
__device__ float g_S1[B_*S_];
__device__ float g_S2[B_*S_];
__device__ float g_attn[TOK*S_];     // last iter only
__device__ float g_cs[B_*S_];
__device__ float g_t1[B_*S_];
__device__ float g_U[B_*S_*D_];
__device__ float g_wkgT[D_*D_];      // wkgT[d][j] = ln_in_g[d]*wk[j][d]
__device__ float g_wkb[D_];          // wk @ ln_in_b + bk

__device__ __forceinline__ float sigmoidf_(float x) { return 1.f / (1.f + expf(-x)); }

// ---------------- prep (merged): transposed g-scaled wk + wkb ---------------
__global__ void k_prep_all(const float* __restrict__ wk, const float* __restrict__ lng,
                           const float* __restrict__ lnb, const float* __restrict__ bk) {
    if (blockIdx.x < 64) {
        __shared__ float tile[32][33];
        int bj = blockIdx.x & 7, bd = blockIdx.x >> 3;
        int j0 = bj * 32, d0 = bd * 32;
        int tx = threadIdx.x & 31, ty = threadIdx.x >> 5;
        #pragma unroll
        for (int r = 0; r < 4; r++)
            tile[ty + 8*r][tx] = wk[(size_t)(j0 + ty + 8*r) * 256 + d0 + tx];
        __syncthreads();
        #pragma unroll
        for (int r = 0; r < 4; r++) {
            int d = d0 + ty + 8*r;
            g_wkgT[(size_t)d * 256 + j0 + tx] = lng[d] * tile[tx][ty + 8*r];
        }
    } else {
        int j = threadIdx.x;
        const float* wr = wk + (size_t)j * 256;
        float acc = bk[j];
        #pragma unroll 4
        for (int e = 0; e < 256; e += 4) {
            float4 w4 = *(const float4*)&wr[e];
            float4 b4 = *(const float4*)&lnb[e];
            acc += w4.x*b4.x + w4.y*b4.y + w4.z*b4.z + w4.w*b4.w;
        }
        g_wkb[j] = acc;
    }
}

// ---------------- K1: per-token mean/rstd ------------------------------------
__global__ void k_meanvar(const float* __restrict__ x) {
    int warp = threadIdx.x >> 5, lane = threadIdx.x & 31;
    int tok = blockIdx.x * 8 + warp;
    const float4* row = (const float4*)(x + (size_t)tok * D_);
    float4 a = row[lane*2], b = row[lane*2+1];
    float s = a.x+a.y+a.z+a.w + b.x+b.y+b.z+b.w;
    float q = a.x*a.x+a.y*a.y+a.z*a.z+a.w*a.w + b.x*b.x+b.y*b.y+b.z*b.z+b.w*b.w;
    #pragma unroll
    for (int o = 16; o; o >>= 1) {
        s += __shfl_xor_sync(0xffffffffu, s, o);
        q += __shfl_xor_sync(0xffffffffu, q, o);
    }
    if (lane == 0) {
        float m = s * (1.f/256.f);
        g_mean[tok] = m;
        g_rstd[tok] = rsqrtf(q * (1.f/256.f) - m*m + EPS);
    }
}

// ---------------- K4: qproj (iteration 0 only: init slots + pg/S1/S2) -------
__global__ void __launch_bounds__(256) k_qproj3(
    const float* __restrict__ g, const float* __restrict__ bln,
    const float* __restrict__ wq, const float* __restrict__ bq,
    const float* __restrict__ noise, const float* __restrict__ mu,
    const float* __restrict__ sigma_raw)
{
    __shared__ __align__(16) float sa[8][256];
    __shared__ __align__(16) float sq[8][256];
    __shared__ float sm[8], sr[8];
    __shared__ float red1[8][8], red2[8][8];
    int b = blockIdx.x, t = threadIdx.x;
    int w = t >> 5, lane = t & 31;

    float sr_ = sigma_raw[t];
    float sp = (sr_ > 20.f) ? sr_ : log1pf(expf(sr_));
    float muv = mu[t];
    #pragma unroll
    for (int s = 0; s < 8; s++) {
        float v = muv + sp * noise[(b*8+s)*256 + t];
        sa[s][t] = v;
        g_slots[(b*8+s)*256 + t] = v;
        g_U[(b*8+s)*256 + t] = 0.f;
    }
    if (t < 8) { g_cs[b*8 + t] = 0.f; g_t1[b*8 + t] = 0.f; }
    __syncthreads();

    {
        float s1 = 0.f, s2 = 0.f;
        #pragma unroll
        for (int e = 0; e < 8; e++) {
            float v = sa[w][lane + e*32];
            s1 += v; s2 += v*v;
        }
        #pragma unroll
        for (int o = 16; o; o >>= 1) {
            s1 += __shfl_xor_sync(0xffffffffu, s1, o);
            s2 += __shfl_xor_sync(0xffffffffu, s2, o);
        }
        if (lane == 0) {
            float m = s1 * (1.f/256.f);
            sm[w] = m;
            sr[w] = rsqrtf(s2 * (1.f/256.f) - m*m + EPS);
        }
    }
    __syncthreads();
    float gt = g[t], bt = bln[t];
    #pragma unroll
    for (int s = 0; s < 8; s++)
        sa[s][t] = (sa[s][t] - sm[s]) * sr[s] * gt + bt;
    __syncthreads();

    {
        float acc[8] = {0,0,0,0,0,0,0,0};
        const float* wr = wq + (size_t)t * 256;
        #pragma unroll 2
        for (int e = 0; e < 256; e += 4) {
            float4 w4 = *(const float4*)&wr[e];
            #pragma unroll
            for (int s = 0; s < 8; s++) {
                float4 a4 = *(const float4*)&sa[s][e];
                acc[s] += w4.x*a4.x + w4.y*a4.y + w4.z*a4.z + w4.w*a4.w;
            }
        }
        float bqt = bq[t];
        #pragma unroll
        for (int s = 0; s < 8; s++) sq[s][t] = acc[s] + bqt;
    }
    __syncthreads();

    float pgv[8] = {0,0,0,0,0,0,0,0};
    {
        const float* wr = g_wkgT + (size_t)t * 256;
        #pragma unroll 2
        for (int e = 0; e < 256; e += 4) {
            float4 w4 = *(const float4*)&wr[e];
            #pragma unroll
            for (int s = 0; s < 8; s++) {
                float4 q4 = *(const float4*)&sq[s][e];
                pgv[s] += w4.x*q4.x + w4.y*q4.y + w4.z*q4.z + w4.w*q4.w;
            }
        }
    }
    float wkbt = g_wkb[t];
    float p2[8];
    #pragma unroll
    for (int s = 0; s < 8; s++) {
        pgv[s] *= SCALE;
        g_p[(b*8+s)*256 + t] = pgv[s];
        p2[s] = sq[s][t] * wkbt;
    }
    #pragma unroll
    for (int s = 0; s < 8; s++) {
        float v1 = pgv[s], v2 = p2[s];
        #pragma unroll
        for (int o = 16; o; o >>= 1) {
            v1 += __shfl_xor_sync(0xffffffffu, v1, o);
            v2 += __shfl_xor_sync(0xffffffffu, v2, o);
        }
        if (lane == 0) { red1[s][w] = v1; red2[s][w] = v2; }
    }
    __syncthreads();
    if (t < 8) {
        float a1 = 0.f, a2 = 0.f;
        #pragma unroll
        for (int i = 0; i < 8; i++) { a1 += red1[t][i]; a2 += red2[t][i]; }
        g_S1[b*8 + t] = a1;
        g_S2[b*8 + t] = a2 * SCALE;
    }
}

// ---------------- K5: fused attn (register pg, 2-token interleaved) ---------
// grid (32 chunks, 32 batches), 128 tokens/CTA
__global__ void __launch_bounds__(256, 2) k_attn7(const float* __restrict__ x,
                                                  int store_attn) {
    __shared__ __align__(16) float sA[32][8];
    int b = blockIdx.y, chunk = blockIdx.x;
    int t = threadIdx.x;
    int wid = t >> 5, lane = t & 31;
    int slot = (lane >> 2) & 7;

    float pg[8][8];
    {
        const float* pb = g_p + b*S_*D_;
        #pragma unroll
        for (int s = 0; s < 8; s++) {
            float4 a = *(const float4*)&pb[s*256 + lane*8];
            float4 c = *(const float4*)&pb[s*256 + lane*8 + 4];
            pg[s][0]=a.x; pg[s][1]=a.y; pg[s][2]=a.z; pg[s][3]=a.w;
            pg[s][4]=c.x; pg[s][5]=c.y; pg[s][6]=c.z; pg[s][7]=c.w;
        }
    }
    float S1l = g_S1[b*8 + slot];
    float S2l = g_S2[b*8 + slot];

    float u[8]  = {0,0,0,0,0,0,0,0};
    float csA = 0.f, t1A = 0.f;
    int base_tok = b*N_ + chunk*128;

    for (int sub = 0; sub < 4; sub++) {
        int sub0 = sub * 32;
        #pragma unroll
        for (int i = 0; i < 4; i += 2) {
            int locA = sub0 + wid*4 + i;
            int nA = base_tok + locA;
            int nB = nA + 1;
            const float* xrA = x + (size_t)nA*256 + lane*8;
            const float* xrB = x + (size_t)nB*256 + lane*8;
            float4 xaA = *(const float4*)xrA;
            float4 xbA = *(const float4*)(xrA + 4);
            float4 xaB = *(const float4*)xrB;
            float4 xbB = *(const float4*)(xrB + 4);

            float dA[8], dB[8];
            #pragma unroll
            for (int s = 0; s < 8; s++) {
                dA[s] = xaA.x*pg[s][0] + xaA.y*pg[s][1] + xaA.z*pg[s][2] + xaA.w*pg[s][3]
                      + xbA.x*pg[s][4] + xbA.y*pg[s][5] + xbA.z*pg[s][6] + xbA.w*pg[s][7];
                dB[s] = xaB.x*pg[s][0] + xaB.y*pg[s][1] + xaB.z*pg[s][2] + xaB.w*pg[s][3]
                      + xbB.x*pg[s][4] + xbB.y*pg[s][5] + xbB.z*pg[s][6] + xbB.w*pg[s][7];
            }
            bool h16 = (lane & 16) != 0;
            float eA0, eA1, eA2, eA3, eB0, eB1, eB2, eB3;
            {
                float rA0 = __shfl_xor_sync(0xffffffffu, dA[0], 16);
                float rB0 = __shfl_xor_sync(0xffffffffu, dB[0], 16);
                float rA1 = __shfl_xor_sync(0xffffffffu, dA[1], 16);
                float rB1 = __shfl_xor_sync(0xffffffffu, dB[1], 16);
                float rA2 = __shfl_xor_sync(0xffffffffu, dA[2], 16);
                float rB2 = __shfl_xor_sync(0xffffffffu, dB[2], 16);
                float rA3 = __shfl_xor_sync(0xffffffffu, dA[3], 16);
                float rB3 = __shfl_xor_sync(0xffffffffu, dB[3], 16);
                float rA4 = __shfl_xor_sync(0xffffffffu, dA[4], 16);
                float rB4 = __shfl_xor_sync(0xffffffffu, dB[4], 16);
                float rA5 = __shfl_xor_sync(0xffffffffu, dA[5], 16);
                float rB5 = __shfl_xor_sync(0xffffffffu, dB[5], 16);
                float rA6 = __shfl_xor_sync(0xffffffffu, dA[6], 16);
                float rB6 = __shfl_xor_sync(0xffffffffu, dB[6], 16);
                float rA7 = __shfl_xor_sync(0xffffffffu, dA[7], 16);
                float rB7 = __shfl_xor_sync(0xffffffffu, dB[7], 16);
                eA0 = h16 ? (dA[4]+rA4) : (dA[0]+rA0);
                eA1 = h16 ? (dA[5]+rA5) : (dA[1]+rA1);
                eA2 = h16 ? (dA[6]+rA6) : (dA[2]+rA2);
                eA3 = h16 ? (dA[7]+rA7) : (dA[3]+rA3);
                eB0 = h16 ? (dB[4]+rB4) : (dB[0]+rB0);
                eB1 = h16 ? (dB[5]+rB5) : (dB[1]+rB1);
                eB2 = h16 ? (dB[6]+rB6) : (dB[2]+rB2);
                eB3 = h16 ? (dB[7]+rB7) : (dB[3]+rB3);
            }
            bool h8 = (lane & 8) != 0;
            float fA0, fA1, fB0, fB1;
            {
                float rA0 = __shfl_xor_sync(0xffffffffu, eA0, 8);
                float rB0 = __shfl_xor_sync(0xffffffffu, eB0, 8);
                float rA1 = __shfl_xor_sync(0xffffffffu, eA1, 8);
                float rB1 = __shfl_xor_sync(0xffffffffu, eB1, 8);
                float rA2 = __shfl_xor_sync(0xffffffffu, eA2, 8);
                float rB2 = __shfl_xor_sync(0xffffffffu, eB2, 8);
                float rA3 = __shfl_xor_sync(0xffffffffu, eA3, 8);
                float rB3 = __shfl_xor_sync(0xffffffffu, eB3, 8);
                fA0 = h8 ? (eA2+rA2) : (eA0+rA0);
                fA1 = h8 ? (eA3+rA3) : (eA1+rA1);
                fB0 = h8 ? (eB2+rB2) : (eB0+rB0);
                fB1 = h8 ? (eB3+rB3) : (eB1+rB1);
            }
            bool h4 = (lane & 4) != 0;
            float vA, vB;
            {
                float rA0 = __shfl_xor_sync(0xffffffffu, fA0, 4);
                float rB0 = __shfl_xor_sync(0xffffffffu, fB0, 4);
                float rA1 = __shfl_xor_sync(0xffffffffu, fA1, 4);
                float rB1 = __shfl_xor_sync(0xffffffffu, fB1, 4);
                vA = h4 ? (fA1+rA1) : (fA0+rA0);
                vB = h4 ? (fB1+rB1) : (fB0+rB0);
            }
            vA += __shfl_xor_sync(0xffffffffu, vA, 2);
            vB += __shfl_xor_sync(0xffffffffu, vB, 2);
            vA += __shfl_xor_sync(0xffffffffu, vA, 1);
            vB += __shfl_xor_sync(0xffffffffu, vB, 1);

            float rA = g_rstd[nA], mA = g_mean[nA];
            float rB = g_rstd[nB], mB = g_mean[nB];
            float rmA = rA * mA, rmB = rB * mB;
            float lgA = rA*vA - rmA*S1l + S2l;
            float lgB = rB*vB - rmB*S1l + S2l;
            float eA = expf(lgA);
            float eB = expf(lgB);
            float sumA = eA, sumB = eB;
            sumA += __shfl_xor_sync(0xffffffffu, sumA, 4);
            sumB += __shfl_xor_sync(0xffffffffu, sumB, 4);
            sumA += __shfl_xor_sync(0xffffffffu, sumA, 8);
            sumB += __shfl_xor_sync(0xffffffffu, sumB, 8);
            sumA += __shfl_xor_sync(0xffffffffu, sumA, 16);
            sumB += __shfl_xor_sync(0xffffffffu, sumB, 16);
            float aA = eA / sumA + 1e-8f;
            float aB = eB / sumB + 1e-8f;
            csA += aA + aB;
            t1A += aA * rmA + aB * rmB;
            if ((lane & 3) == 0) {
                sA[locA - sub0][slot]     = aA * rA;
                sA[locA - sub0 + 1][slot] = aB * rB;
                if (store_attn) {
                    g_attn[(size_t)nA*8 + slot] = aA;
                    g_attn[(size_t)nB*8 + slot] = aB;
                }
            }
        }
        __syncthreads();
        const float* xcol = x + (size_t)(base_tok + sub0)*256 + t;
        #pragma unroll 8
        for (int i = 0; i < 32; i++) {
            float xv = xcol[(size_t)i*256];
            float4 p0 = *(const float4*)&sA[i][0];
            float4 p1 = *(const float4*)&sA[i][4];
            u[0] += p0.x*xv; u[1] += p0.y*xv; u[2] += p0.z*xv; u[3] += p0.w*xv;
            u[4] += p1.x*xv; u[5] += p1.y*xv; u[6] += p1.z*xv; u[7] += p1.w*xv;
        }
        __syncthreads();
    }

    #pragma unroll
    for (int s = 0; s < 8; s++)
        atomicAdd(&g_U[(b*8+s)*256 + t], u[s]);
    if ((lane & 3) == 0) {
        atomicAdd(&g_cs[b*8 + slot], csA);
        atomicAdd(&g_t1[b*8 + slot], t1A);
    }
}

// ---------------- K7: GRU + LN + MLP, 4 slots/CTA (+ fused next-iter qproj) -
__global__ void __launch_bounds__(256) k_gruq4(
    const float* __restrict__ lng_in, const float* __restrict__ lnb_in,
    const float* __restrict__ wv,   const float* __restrict__ bv,
    const float* __restrict__ w_ih, const float* __restrict__ w_hh,
    const float* __restrict__ b_ih, const float* __restrict__ b_hh,
    const float* __restrict__ lng,  const float* __restrict__ lnb,
    const float* __restrict__ w1,   const float* __restrict__ b1,
    const float* __restrict__ w2,   const float* __restrict__ b2,
    const float* __restrict__ lsg,  const float* __restrict__ lsb,
    const float* __restrict__ wq,   const float* __restrict__ bq,
    int do_qproj, float* __restrict__ out_slots)
{
    __shared__ __align__(16) float szn[4][256];
    __shared__ __align__(16) float su[4][256];
    __shared__ __align__(16) float sh[4][256];
    __shared__ __align__(16) float sa[4][256];
    __shared__ __align__(16) float sh1[4][512];
    __shared__ float sm[4], sr2[4];
    __shared__ float red1[4][8], red2[4][8];

    int b = blockIdx.x >> 1;
    int p = blockIdx.x & 1;
    int row0 = b*8 + p*4;
    int t = threadIdx.x;
    int w = t >> 5, lane = t & 31;

    #pragma unroll
    for (int sl = 0; sl < 4; sl++) {
        int row = row0 + sl;
        float csv = g_cs[row], t1v = g_t1[row];
        float Ut = g_U[row*256 + t];
        szn[sl][t] = lng_in[t] * (Ut - t1v) / csv + lnb_in[t];
        sh[sl][t] = g_slots[row*256 + t];
    }
    __syncthreads();

    {
        float a[4] = {0,0,0,0};
        const float* wr = wv + (size_t)t * 256;
        #pragma unroll 2
        for (int e = 0; e < 256; e += 4) {
            float4 w4 = *(const float4*)&wr[e];
            #pragma unroll
            for (int sl = 0; sl < 4; sl++) {
                float4 z = *(const float4*)&szn[sl][e];
                a[sl] += w4.x*z.x + w4.y*z.y + w4.z*z.z + w4.w*z.w;
            }
        }
        float bvt = bv[t];
        #pragma unroll
        for (int sl = 0; sl < 4; sl++) su[sl][t] = a[sl] + bvt;
    }
    __syncthreads();

    float xr[4], xz[4], xn[4], hr[4], hz[4], hn[4];
    #pragma unroll
    for (int sl = 0; sl < 4; sl++) {
        xr[sl] = b_ih[t]; xz[sl] = b_ih[256+t]; xn[sl] = b_ih[512+t];
        hr[sl] = b_hh[t]; hz[sl] = b_hh[256+t]; hn[sl] = b_hh[512+t];
    }
    const float* wir = w_ih + (size_t)t*256;
    const float* wiz = w_ih + (size_t)(256+t)*256;
    const float* win = w_ih + (size_t)(512+t)*256;
    const float* whr = w_hh + (size_t)t*256;
    const float* whz = w_hh + (size_t)(256+t)*256;
    const float* whn = w_hh + (size_t)(512+t)*256;

    for (int e = 0; e < 256; e += 4) {
        float4 wr4 = *(const float4*)&wir[e];
        float4 wz4 = *(const float4*)&wiz[e];
        float4 wn4 = *(const float4*)&win[e];
        float4 vr4 = *(const float4*)&whr[e];
        float4 vz4 = *(const float4*)&whz[e];
        float4 vn4 = *(const float4*)&whn[e];
        #pragma unroll
        for (int sl = 0; sl < 4; sl++) {
            float4 u4 = *(const float4*)&su[sl][e];
            float4 h4 = *(const float4*)&sh[sl][e];
            xr[sl] += wr4.x*u4.x + wr4.y*u4.y + wr4.z*u4.z + wr4.w*u4.w;
            xz[sl] += wz4.x*u4.x + wz4.y*u4.y + wz4.z*u4.z + wz4.w*u4.w;
            xn[sl] += wn4.x*u4.x + wn4.y*u4.y + wn4.z*u4.z + wn4.w*u4.w;
            hr[sl] += vr4.x*h4.x + vr4.y*h4.y + vr4.z*h4.z + vr4.w*h4.w;
            hz[sl] += vz4.x*h4.x + vz4.y*h4.y + vz4.z*h4.z + vz4.w*h4.w;
            hn[sl] += vn4.x*h4.x + vn4.y*h4.y + vn4.z*h4.z + vn4.w*h4.w;
        }
    }
    float hnew[4];
    #pragma unroll
    for (int sl = 0; sl < 4; sl++) {
        float r = sigmoidf_(xr[sl] + hr[sl]);
        float z = sigmoidf_(xz[sl] + hz[sl]);
        float nn = tanhf(xn[sl] + r*hn[sl]);
        hnew[sl] = (1.f - z)*nn + z*sh[sl][t];
    }
    __syncthreads();
    #pragma unroll
    for (int sl = 0; sl < 4; sl++) su[sl][t] = hnew[sl];
    __syncthreads();
    if (w < 4) {
        float s1 = 0.f, s2 = 0.f;
        #pragma unroll
        for (int e = 0; e < 8; e++) {
            float v = su[w][lane + e*32];
            s1 += v; s2 += v*v;
        }
        #pragma unroll
        for (int o = 16; o; o >>= 1) {
            s1 += __shfl_xor_sync(0xffffffffu, s1, o);
            s2 += __shfl_xor_sync(0xffffffffu, s2, o);
        }
        if (lane == 0) {
            float m = s1 * (1.f/256.f);
            sm[w] = m;
            sr2[w] = rsqrtf(s2 * (1.f/256.f) - m*m + EPS);
        }
    }
    __syncthreads();
    float gt = lng[t], bt = lnb[t];
    #pragma unroll
    for (int sl = 0; sl < 4; sl++)
        sa[sl][t] = (hnew[sl] - sm[sl]) * sr2[sl] * gt + bt;
    __syncthreads();

    float a1[4] = {b1[t], b1[t], b1[t], b1[t]};
    float a2[4] = {b1[256+t], b1[256+t], b1[256+t], b1[256+t]};
    const float* w1a = w1 + (size_t)t*256;
    const float* w1b = w1 + (size_t)(256+t)*256;
    for (int e = 0; e < 256; e += 4) {
        float4 wa = *(const float4*)&w1a[e];
        float4 wb = *(const float4*)&w1b[e];
        #pragma unroll
        for (int sl = 0; sl < 4; sl++) {
            float4 s4 = *(const float4*)&sa[sl][e];
            a1[sl] += wa.x*s4.x + wa.y*s4.y + wa.z*s4.z + wa.w*s4.w;
            a2[sl] += wb.x*s4.x + wb.y*s4.y + wb.z*s4.z + wb.w*s4.w;
        }
    }
    #pragma unroll
    for (int sl = 0; sl < 4; sl++) {
        sh1[sl][t]     = fmaxf(a1[sl], 0.f);
        sh1[sl][256+t] = fmaxf(a2[sl], 0.f);
    }
    __syncthreads();

    float o[4] = {b2[t], b2[t], b2[t], b2[t]};
    const float* w2r = w2 + (size_t)t*512;
    for (int e = 0; e < 512; e += 4) {
        float4 w4 = *(const float4*)&w2r[e];
        #pragma unroll
        for (int sl = 0; sl < 4; sl++) {
            float4 h4 = *(const float4*)&sh1[sl][e];
            o[sl] += w4.x*h4.x + w4.y*h4.y + w4.z*h4.z + w4.w*h4.w;
        }
    }
    float res[4];
    #pragma unroll
    for (int sl = 0; sl < 4; sl++) {
        res[sl] = hnew[sl] + o[sl];
        g_slots[(row0+sl)*256 + t] = res[sl];
        if (out_slots) out_slots[(row0+sl)*256 + t] = res[sl];
    }

    if (!do_qproj) return;

    // ======== fused qproj for next iteration (4 slots) ========
    __syncthreads();
    #pragma unroll
    for (int sl = 0; sl < 4; sl++) {
        sh[sl][t] = res[sl];
        g_U[(row0+sl)*256 + t] = 0.f;
    }
    if (t < 4) { g_cs[row0 + t] = 0.f; g_t1[row0 + t] = 0.f; }
    __syncthreads();
    if (w < 4) {
        float s1 = 0.f, s2 = 0.f;
        #pragma unroll
        for (int e = 0; e < 8; e++) {
            float v = sh[w][lane + e*32];
            s1 += v; s2 += v*v;
        }
        #pragma unroll
        for (int oo = 16; oo; oo >>= 1) {
            s1 += __shfl_xor_sync(0xffffffffu, s1, oo);
            s2 += __shfl_xor_sync(0xffffffffu, s2, oo);
        }
        if (lane == 0) {
            float m = s1 * (1.f/256.f);
            sm[w] = m;
            sr2[w] = rsqrtf(s2 * (1.f/256.f) - m*m + EPS);
        }
    }
    __syncthreads();
    float gst = lsg[t], bst = lsb[t];
    #pragma unroll
    for (int sl = 0; sl < 4; sl++)
        sa[sl][t] = (res[sl] - sm[sl]) * sr2[sl] * gst + bst;
    __syncthreads();

    // q[sl][t] = sa[sl]·wq[t,:] + bq[t] -> szn
    {
        float q[4] = {0,0,0,0};
        const float* wr = wq + (size_t)t * 256;
        #pragma unroll 2
        for (int e = 0; e < 256; e += 4) {
            float4 w4 = *(const float4*)&wr[e];
            #pragma unroll
            for (int sl = 0; sl < 4; sl++) {
                float4 s4 = *(const float4*)&sa[sl][e];
                q[sl] += w4.x*s4.x + w4.y*s4.y + w4.z*s4.z + w4.w*s4.w;
            }
        }
        float bqt = bq[t];
        #pragma unroll
        for (int sl = 0; sl < 4; sl++) szn[sl][t] = q[sl] + bqt;
    }
    __syncthreads();

    // pg[sl][t] = SCALE * q[sl]·wkgT[t,:]; S1, S2
    float pgv[4] = {0,0,0,0};
    {
        const float* wr = g_wkgT + (size_t)t * 256;
        #pragma unroll 2
        for (int e = 0; e < 256; e += 4) {
            float4 w4 = *(const float4*)&wr[e];
            #pragma unroll
            for (int sl = 0; sl < 4; sl++) {
                float4 q4 = *(const float4*)&szn[sl][e];
                pgv[sl] += w4.x*q4.x + w4.y*q4.y + w4.z*q4.z + w4.w*q4.w;
            }
        }
    }
    float wkbt = g_wkb[t];
    float p2v[4];
    #pragma unroll
    for (int sl = 0; sl < 4; sl++) {
        pgv[sl] *= SCALE;
        g_p[(row0+sl)*256 + t] = pgv[sl];
        p2v[sl] = szn[sl][t] * wkbt;
    }
    #pragma unroll
    for (int sl = 0; sl < 4; sl++) {
        float v1 = pgv[sl], v2 = p2v[sl];
        #pragma unroll
        for (int oo = 16; oo; oo >>= 1) {
            v1 += __shfl_xor_sync(0xffffffffu, v1, oo);
            v2 += __shfl_xor_sync(0xffffffffu, v2, oo);
        }
        if (lane == 0) { red1[sl][w] = v1; red2[sl][w] = v2; }
    }
    __syncthreads();
    if (t < 4) {
        float a1s = 0.f, a2s = 0.f;
        #pragma unroll
        for (int i = 0; i < 8; i++) { a1s += red1[t][i]; a2s += red2[t][i]; }
        g_S1[row0 + t] = a1s;
        g_S2[row0 + t] = a2s * SCALE;
    }
}

// ---------------- K8: final attn normalize to d_out --------------------------
__global__ void k_attn_out(float* __restrict__ dst) {
    int i = blockIdx.x*blockDim.x + threadIdx.x;
    if (i < TOK*S_) {
        int s = i & 7;
        int b = i >> 15;
        dst[i] = g_attn[i] / g_cs[b*8 + s];
    }
}

// ---------------- host --------------------------------------------------------
extern "C" void kernel_launch(void* const* d_in, const int* in_sizes, int n_in,
                              void* d_out, int out_size) {
    const float* inputs     = (const float*)d_in[0];
    const float* init_noise = (const float*)d_in[1];
    const float* mu         = (const float*)d_in[2];
    const float* sigma_raw  = (const float*)d_in[3];
    const float* ln_in_g    = (const float*)d_in[4];
    const float* ln_in_b    = (const float*)d_in[5];
    const float* ln_s_g     = (const float*)d_in[6];
    const float* ln_s_b     = (const float*)d_in[7];
    const float* ln_m_g     = (const float*)d_in[8];
    const float* ln_m_b     = (const float*)d_in[9];
    const float* wq         = (const float*)d_in[10];
    const float* bq         = (const float*)d_in[11];
    const float* wk         = (const float*)d_in[12];
    const float* bk         = (const float*)d_in[13];
    const float* wv         = (const float*)d_in[14];
    const float* bv         = (const float*)d_in[15];
    const float* w_ih       = (const float*)d_in[16];
    const float* w_hh       = (const float*)d_in[17];
    const float* b_ih       = (const float*)d_in[18];
    const float* b_hh       = (const float*)d_in[19];
    const float* w1         = (const float*)d_in[20];
    const float* b1         = (const float*)d_in[21];
    const float* w2         = (const float*)d_in[22];
    const float* b2         = (const float*)d_in[23];
    float* out = (float*)d_out;

    k_prep_all<<<65, 256>>>(wk, ln_in_g, ln_in_b, bk);
    k_meanvar<<<TOK/8, 256>>>(inputs);
    k_qproj3<<<B_, 256>>>(ln_s_g, ln_s_b, wq, bq, init_noise, mu, sigma_raw);

    for (int it = 0; it < 3; ++it) {
        bool last = (it == 2);
        k_attn7<<<dim3(32, B_), 256>>>(inputs, last ? 1 : 0);
        k_gruq4<<<B_*2, 256>>>(ln_in_g, ln_in_b, wv, bv,
                               w_ih, w_hh, b_ih, b_hh, ln_m_g, ln_m_b,
                               w1, b1, w2, b2,
                               ln_s_g, ln_s_b, wq, bq,
                               last ? 0 : 1, last ? out : nullptr);
    }
    k_attn_out<<<(TOK*S_ + 255)/256, 256>>>(out + B_*S_*D_);
}

// round 15
// speedup vs baseline: 1.4562x; 1.0203x over previous
#include <cuda_runtime.h>
#include <cstdint>
#include <math.h>

#define B_   32
#define N_   4096
#define D_   256
#define S_   8
#define H_   512
#define TOK  (B_*N_)      // 131072
#define EPS  1e-5f
#define SCALE 0.0625f     // 256^-0.5

// ---------------- scratch (device globals) ----------------------------------
__device__ float g_mean[TOK];
__device__ float g_rstd[TOK];
__device__ float g_slots[B_*S_*D_];
__device__ float g_p[B_*S_*D_];      // pg = SCALE * g ∘ (q @ wk)
__device__ float g_S1[B_*S_];
__device__ float g_S2[B_*S_];
__device__ float g_attn[TOK*S_];     // last iter only
__device__ float g_cs[B_*S_];
__device__ float g_t1[B_*S_];
__device__ float g_U[B_*S_*D_];
__device__ float g_wkgT[D_*D_];      // wkgT[d][j] = ln_in_g[d]*wk[j][d]
__device__ float g_wkb[D_];          // wk @ ln_in_b + bk

__device__ __forceinline__ float sigmoidf_(float x) { return 1.f / (1.f + expf(-x)); }

// ---------------- packed f32x2 helpers (sm_100+ baseline PTX) ----------------
__device__ __forceinline__ unsigned long long f2pk(float lo, float hi) {
    unsigned long long r;
    asm("mov.b64 %0, {%1,%2};" : "=l"(r) : "f"(lo), "f"(hi));
    return r;
}
__device__ __forceinline__ unsigned long long fma2_(unsigned long long a,
                                                    unsigned long long b,
                                                    unsigned long long c) {
    unsigned long long d;
    asm("fma.rn.f32x2 %0, %1, %2, %3;" : "=l"(d) : "l"(a), "l"(b), "l"(c));
    return d;
}
__device__ __forceinline__ unsigned long long mul2_(unsigned long long a,
                                                    unsigned long long b) {
    unsigned long long d;
    asm("mul.rn.f32x2 %0, %1, %2;" : "=l"(d) : "l"(a), "l"(b));
    return d;
}
__device__ __forceinline__ float2 f2up(unsigned long long v) {
    float lo, hi;
    asm("mov.b64 {%0,%1}, %2;" : "=f"(lo), "=f"(hi) : "l"(v));
    return make_float2(lo, hi);
}

// ---------------- prep (merged): transposed g-scaled wk + wkb ---------------
__global__ void k_prep_all(const float* __restrict__ wk, const float* __restrict__ lng,
                           const float* __restrict__ lnb, const float* __restrict__ bk) {
    if (blockIdx.x < 64) {
        __shared__ float tile[32][33];
        int bj = blockIdx.x & 7, bd = blockIdx.x >> 3;
        int j0 = bj * 32, d0 = bd * 32;
        int tx = threadIdx.x & 31, ty = threadIdx.x >> 5;
        #pragma unroll
        for (int r = 0; r < 4; r++)
            tile[ty + 8*r][tx] = wk[(size_t)(j0 + ty + 8*r) * 256 + d0 + tx];
        __syncthreads();
        #pragma unroll
        for (int r = 0; r < 4; r++) {
            int d = d0 + ty + 8*r;
            g_wkgT[(size_t)d * 256 + j0 + tx] = lng[d] * tile[tx][ty + 8*r];
        }
    } else {
        int j = threadIdx.x;
        const float* wr = wk + (size_t)j * 256;
        float acc = bk[j];
        #pragma unroll 4
        for (int e = 0; e < 256; e += 4) {
            float4 w4 = *(const float4*)&wr[e];
            float4 b4 = *(const float4*)&lnb[e];
            acc += w4.x*b4.x + w4.y*b4.y + w4.z*b4.z + w4.w*b4.w;
        }
        g_wkb[j] = acc;
    }
}

// ---------------- K1: per-token mean/rstd ------------------------------------
__global__ void k_meanvar(const float* __restrict__ x) {
    int warp = threadIdx.x >> 5, lane = threadIdx.x & 31;
    int tok = blockIdx.x * 8 + warp;
    const float4* row = (const float4*)(x + (size_t)tok * D_);
    float4 a = row[lane*2], b = row[lane*2+1];
    float s = a.x+a.y+a.z+a.w + b.x+b.y+b.z+b.w;
    float q = a.x*a.x+a.y*a.y+a.z*a.z+a.w*a.w + b.x*b.x+b.y*b.y+b.z*b.z+b.w*b.w;
    #pragma unroll
    for (int o = 16; o; o >>= 1) {
        s += __shfl_xor_sync(0xffffffffu, s, o);
        q += __shfl_xor_sync(0xffffffffu, q, o);
    }
    if (lane == 0) {
        float m = s * (1.f/256.f);
        g_mean[tok] = m;
        g_rstd[tok] = rsqrtf(q * (1.f/256.f) - m*m + EPS);
    }
}

// ---------------- K4: qproj (iteration 0 only: init slots + pg/S1/S2) -------
__global__ void __launch_bounds__(256) k_qproj3(
    const float* __restrict__ g, const float* __restrict__ bln,
    const float* __restrict__ wq, const float* __restrict__ bq,
    const float* __restrict__ noise, const float* __restrict__ mu,
    const float* __restrict__ sigma_raw)
{
    __shared__ __align__(16) float sa[8][256];
    __shared__ __align__(16) float sq[8][256];
    __shared__ float sm[8], sr[8];
    __shared__ float red1[8][8], red2[8][8];
    int b = blockIdx.x, t = threadIdx.x;
    int w = t >> 5, lane = t & 31;

    float sr_ = sigma_raw[t];
    float sp = (sr_ > 20.f) ? sr_ : log1pf(expf(sr_));
    float muv = mu[t];
    #pragma unroll
    for (int s = 0; s < 8; s++) {
        float v = muv + sp * noise[(b*8+s)*256 + t];
        sa[s][t] = v;
        g_slots[(b*8+s)*256 + t] = v;
        g_U[(b*8+s)*256 + t] = 0.f;
    }
    if (t < 8) { g_cs[b*8 + t] = 0.f; g_t1[b*8 + t] = 0.f; }
    __syncthreads();

    {
        float s1 = 0.f, s2 = 0.f;
        #pragma unroll
        for (int e = 0; e < 8; e++) {
            float v = sa[w][lane + e*32];
            s1 += v; s2 += v*v;
        }
        #pragma unroll
        for (int o = 16; o; o >>= 1) {
            s1 += __shfl_xor_sync(0xffffffffu, s1, o);
            s2 += __shfl_xor_sync(0xffffffffu, s2, o);
        }
        if (lane == 0) {
            float m = s1 * (1.f/256.f);
            sm[w] = m;
            sr[w] = rsqrtf(s2 * (1.f/256.f) - m*m + EPS);
        }
    }
    __syncthreads();
    float gt = g[t], bt = bln[t];
    #pragma unroll
    for (int s = 0; s < 8; s++)
        sa[s][t] = (sa[s][t] - sm[s]) * sr[s] * gt + bt;
    __syncthreads();

    {
        float acc[8] = {0,0,0,0,0,0,0,0};
        const float* wr = wq + (size_t)t * 256;
        #pragma unroll 2
        for (int e = 0; e < 256; e += 4) {
            float4 w4 = *(const float4*)&wr[e];
            #pragma unroll
            for (int s = 0; s < 8; s++) {
                float4 a4 = *(const float4*)&sa[s][e];
                acc[s] += w4.x*a4.x + w4.y*a4.y + w4.z*a4.z + w4.w*a4.w;
            }
        }
        float bqt = bq[t];
        #pragma unroll
        for (int s = 0; s < 8; s++) sq[s][t] = acc[s] + bqt;
    }
    __syncthreads();

    float pgv[8] = {0,0,0,0,0,0,0,0};
    {
        const float* wr = g_wkgT + (size_t)t * 256;
        #pragma unroll 2
        for (int e = 0; e < 256; e += 4) {
            float4 w4 = *(const float4*)&wr[e];
            #pragma unroll
            for (int s = 0; s < 8; s++) {
                float4 q4 = *(const float4*)&sq[s][e];
                pgv[s] += w4.x*q4.x + w4.y*q4.y + w4.z*q4.z + w4.w*q4.w;
            }
        }
    }
    float wkbt = g_wkb[t];
    float p2[8];
    #pragma unroll
    for (int s = 0; s < 8; s++) {
        pgv[s] *= SCALE;
        g_p[(b*8+s)*256 + t] = pgv[s];
        p2[s] = sq[s][t] * wkbt;
    }
    #pragma unroll
    for (int s = 0; s < 8; s++) {
        float v1 = pgv[s], v2 = p2[s];
        #pragma unroll
        for (int o = 16; o; o >>= 1) {
            v1 += __shfl_xor_sync(0xffffffffu, v1, o);
            v2 += __shfl_xor_sync(0xffffffffu, v2, o);
        }
        if (lane == 0) { red1[s][w] = v1; red2[s][w] = v2; }
    }
    __syncthreads();
    if (t < 8) {
        float a1 = 0.f, a2 = 0.f;
        #pragma unroll
        for (int i = 0; i < 8; i++) { a1 += red1[t][i]; a2 += red2[t][i]; }
        g_S1[b*8 + t] = a1;
        g_S2[b*8 + t] = a2 * SCALE;
    }
}

// ---------------- K5: fused attn (packed f32x2 FMA, 2-token interleaved) ----
// grid (32 chunks, 32 batches), 128 tokens/CTA
__global__ void __launch_bounds__(256, 2) k_attn8(const float* __restrict__ x,
                                                  int store_attn) {
    __shared__ __align__(16) float sA[32][8];
    int b = blockIdx.y, chunk = blockIdx.x;
    int t = threadIdx.x;
    int wid = t >> 5, lane = t & 31;
    int slot = (lane >> 2) & 7;

    unsigned long long pgp[8][4];
    {
        const float* pb = g_p + b*S_*D_;
        #pragma unroll
        for (int s = 0; s < 8; s++) {
            float4 a = *(const float4*)&pb[s*256 + lane*8];
            float4 c = *(const float4*)&pb[s*256 + lane*8 + 4];
            pgp[s][0] = f2pk(a.x, a.y);
            pgp[s][1] = f2pk(a.z, a.w);
            pgp[s][2] = f2pk(c.x, c.y);
            pgp[s][3] = f2pk(c.z, c.w);
        }
    }
    float S1l = g_S1[b*8 + slot];
    float S2l = g_S2[b*8 + slot];

    unsigned long long u2[4];
    #pragma unroll
    for (int j = 0; j < 4; j++) u2[j] = f2pk(0.f, 0.f);
    float csA = 0.f, t1A = 0.f;
    int base_tok = b*N_ + chunk*128;

    for (int sub = 0; sub < 4; sub++) {
        int sub0 = sub * 32;
        #pragma unroll
        for (int i = 0; i < 4; i += 2) {
            int locA = sub0 + wid*4 + i;
            int nA = base_tok + locA;
            int nB = nA + 1;
            const float* xrA = x + (size_t)nA*256 + lane*8;
            const float* xrB = x + (size_t)nB*256 + lane*8;
            float4 xaA = *(const float4*)xrA;
            float4 xbA = *(const float4*)(xrA + 4);
            float4 xaB = *(const float4*)xrB;
            float4 xbB = *(const float4*)(xrB + 4);
            unsigned long long xpA[4], xpB[4];
            xpA[0] = f2pk(xaA.x, xaA.y); xpA[1] = f2pk(xaA.z, xaA.w);
            xpA[2] = f2pk(xbA.x, xbA.y); xpA[3] = f2pk(xbA.z, xbA.w);
            xpB[0] = f2pk(xaB.x, xaB.y); xpB[1] = f2pk(xaB.z, xaB.w);
            xpB[2] = f2pk(xbB.x, xbB.y); xpB[3] = f2pk(xbB.z, xbB.w);

            float dA[8], dB[8];
            #pragma unroll
            for (int s = 0; s < 8; s++) {
                unsigned long long aA = mul2_(xpA[0], pgp[s][0]);
                unsigned long long aB = mul2_(xpB[0], pgp[s][0]);
                aA = fma2_(xpA[1], pgp[s][1], aA);
                aB = fma2_(xpB[1], pgp[s][1], aB);
                aA = fma2_(xpA[2], pgp[s][2], aA);
                aB = fma2_(xpB[2], pgp[s][2], aB);
                aA = fma2_(xpA[3], pgp[s][3], aA);
                aB = fma2_(xpB[3], pgp[s][3], aB);
                float2 fA = f2up(aA), fB = f2up(aB);
                dA[s] = fA.x + fA.y;
                dB[s] = fB.x + fB.y;
            }
            bool h16 = (lane & 16) != 0;
            float eA0, eA1, eA2, eA3, eB0, eB1, eB2, eB3;
            {
                float rA0 = __shfl_xor_sync(0xffffffffu, dA[0], 16);
                float rB0 = __shfl_xor_sync(0xffffffffu, dB[0], 16);
                float rA1 = __shfl_xor_sync(0xffffffffu, dA[1], 16);
                float rB1 = __shfl_xor_sync(0xffffffffu, dB[1], 16);
                float rA2 = __shfl_xor_sync(0xffffffffu, dA[2], 16);
                float rB2 = __shfl_xor_sync(0xffffffffu, dB[2], 16);
                float rA3 = __shfl_xor_sync(0xffffffffu, dA[3], 16);
                float rB3 = __shfl_xor_sync(0xffffffffu, dB[3], 16);
                float rA4 = __shfl_xor_sync(0xffffffffu, dA[4], 16);
                float rB4 = __shfl_xor_sync(0xffffffffu, dB[4], 16);
                float rA5 = __shfl_xor_sync(0xffffffffu, dA[5], 16);
                float rB5 = __shfl_xor_sync(0xffffffffu, dB[5], 16);
                float rA6 = __shfl_xor_sync(0xffffffffu, dA[6], 16);
                float rB6 = __shfl_xor_sync(0xffffffffu, dB[6], 16);
                float rA7 = __shfl_xor_sync(0xffffffffu, dA[7], 16);
                float rB7 = __shfl_xor_sync(0xffffffffu, dB[7], 16);
                eA0 = h16 ? (dA[4]+rA4) : (dA[0]+rA0);
                eA1 = h16 ? (dA[5]+rA5) : (dA[1]+rA1);
                eA2 = h16 ? (dA[6]+rA6) : (dA[2]+rA2);
                eA3 = h16 ? (dA[7]+rA7) : (dA[3]+rA3);
                eB0 = h16 ? (dB[4]+rB4) : (dB[0]+rB0);
                eB1 = h16 ? (dB[5]+rB5) : (dB[1]+rB1);
                eB2 = h16 ? (dB[6]+rB6) : (dB[2]+rB2);
                eB3 = h16 ? (dB[7]+rB7) : (dB[3]+rB3);
            }
            bool h8 = (lane & 8) != 0;
            float fA0, fA1, fB0, fB1;
            {
                float rA0 = __shfl_xor_sync(0xffffffffu, eA0, 8);
                float rB0 = __shfl_xor_sync(0xffffffffu, eB0, 8);
                float rA1 = __shfl_xor_sync(0xffffffffu, eA1, 8);
                float rB1 = __shfl_xor_sync(0xffffffffu, eB1, 8);
                float rA2 = __shfl_xor_sync(0xffffffffu, eA2, 8);
                float rB2 = __shfl_xor_sync(0xffffffffu, eB2, 8);
                float rA3 = __shfl_xor_sync(0xffffffffu, eA3, 8);
                float rB3 = __shfl_xor_sync(0xffffffffu, eB3, 8);
                fA0 = h8 ? (eA2+rA2) : (eA0+rA0);
                fA1 = h8 ? (eA3+rA3) : (eA1+rA1);
                fB0 = h8 ? (eB2+rB2) : (eB0+rB0);
                fB1 = h8 ? (eB3+rB3) : (eB1+rB1);
            }
            bool h4 = (lane & 4) != 0;
            float vA, vB;
            {
                float rA0 = __shfl_xor_sync(0xffffffffu, fA0, 4);
                float rB0 = __shfl_xor_sync(0xffffffffu, fB0, 4);
                float rA1 = __shfl_xor_sync(0xffffffffu, fA1, 4);
                float rB1 = __shfl_xor_sync(0xffffffffu, fB1, 4);
                vA = h4 ? (fA1+rA1) : (fA0+rA0);
                vB = h4 ? (fB1+rB1) : (fB0+rB0);
            }
            vA += __shfl_xor_sync(0xffffffffu, vA, 2);
            vB += __shfl_xor_sync(0xffffffffu, vB, 2);
            vA += __shfl_xor_sync(0xffffffffu, vA, 1);
            vB += __shfl_xor_sync(0xffffffffu, vB, 1);

            float rA = g_rstd[nA], mA = g_mean[nA];
            float rB = g_rstd[nB], mB = g_mean[nB];
            float rmA = rA * mA, rmB = rB * mB;
            float lgA = rA*vA - rmA*S1l + S2l;
            float lgB = rB*vB - rmB*S1l + S2l;
            float eA = expf(lgA);
            float eB = expf(lgB);
            float sumA = eA, sumB = eB;
            sumA += __shfl_xor_sync(0xffffffffu, sumA, 4);
            sumB += __shfl_xor_sync(0xffffffffu, sumB, 4);
            sumA += __shfl_xor_sync(0xffffffffu, sumA, 8);
            sumB += __shfl_xor_sync(0xffffffffu, sumB, 8);
            sumA += __shfl_xor_sync(0xffffffffu, sumA, 16);
            sumB += __shfl_xor_sync(0xffffffffu, sumB, 16);
            float aA = eA / sumA + 1e-8f;
            float aB = eB / sumB + 1e-8f;
            csA += aA + aB;
            t1A += aA * rmA + aB * rmB;
            if ((lane & 3) == 0) {
                sA[locA - sub0][slot]     = aA * rA;
                sA[locA - sub0 + 1][slot] = aB * rB;
                if (store_attn) {
                    g_attn[(size_t)nA*8 + slot] = aA;
                    g_attn[(size_t)nB*8 + slot] = aB;
                }
            }
        }
        __syncthreads();
        const float* xcol = x + (size_t)(base_tok + sub0)*256 + t;
        #pragma unroll 8
        for (int i = 0; i < 32; i++) {
            float xv = xcol[(size_t)i*256];
            unsigned long long xvp = f2pk(xv, xv);
            const unsigned long long* sp = (const unsigned long long*)&sA[i][0];
            u2[0] = fma2_(sp[0], xvp, u2[0]);
            u2[1] = fma2_(sp[1], xvp, u2[1]);
            u2[2] = fma2_(sp[2], xvp, u2[2]);
            u2[3] = fma2_(sp[3], xvp, u2[3]);
        }
        __syncthreads();
    }

    #pragma unroll
    for (int j = 0; j < 4; j++) {
        float2 uv = f2up(u2[j]);
        atomicAdd(&g_U[(b*8 + 2*j)    *256 + t], uv.x);
        atomicAdd(&g_U[(b*8 + 2*j + 1)*256 + t], uv.y);
    }
    if ((lane & 3) == 0) {
        atomicAdd(&g_cs[b*8 + slot], csA);
        atomicAdd(&g_t1[b*8 + slot], t1A);
    }
}

// ---------------- K7: GRU + LN + MLP, 4 slots/CTA (+ fused next-iter qproj) -
__global__ void __launch_bounds__(256) k_gruq4(
    const float* __restrict__ lng_in, const float* __restrict__ lnb_in,
    const float* __restrict__ wv,   const float* __restrict__ bv,
    const float* __restrict__ w_ih, const float* __restrict__ w_hh,
    const float* __restrict__ b_ih, const float* __restrict__ b_hh,
    const float* __restrict__ lng,  const float* __restrict__ lnb,
    const float* __restrict__ w1,   const float* __restrict__ b1,
    const float* __restrict__ w2,   const float* __restrict__ b2,
    const float* __restrict__ lsg,  const float* __restrict__ lsb,
    const float* __restrict__ wq,   const float* __restrict__ bq,
    int do_qproj, float* __restrict__ out_slots)
{
    __shared__ __align__(16) float szn[4][256];
    __shared__ __align__(16) float su[4][256];
    __shared__ __align__(16) float sh[4][256];
    __shared__ __align__(16) float sa[4][256];
    __shared__ __align__(16) float sh1[4][512];
    __shared__ float sm[4], sr2[4];
    __shared__ float red1[4][8], red2[4][8];

    int b = blockIdx.x >> 1;
    int p = blockIdx.x & 1;
    int row0 = b*8 + p*4;
    int t = threadIdx.x;
    int w = t >> 5, lane = t & 31;

    #pragma unroll
    for (int sl = 0; sl < 4; sl++) {
        int row = row0 + sl;
        float csv = g_cs[row], t1v = g_t1[row];
        float Ut = g_U[row*256 + t];
        szn[sl][t] = lng_in[t] * (Ut - t1v) / csv + lnb_in[t];
        sh[sl][t] = g_slots[row*256 + t];
    }
    __syncthreads();

    {
        float a[4] = {0,0,0,0};
        const float* wr = wv + (size_t)t * 256;
        #pragma unroll 2
        for (int e = 0; e < 256; e += 4) {
            float4 w4 = *(const float4*)&wr[e];
            #pragma unroll
            for (int sl = 0; sl < 4; sl++) {
                float4 z = *(const float4*)&szn[sl][e];
                a[sl] += w4.x*z.x + w4.y*z.y + w4.z*z.z + w4.w*z.w;
            }
        }
        float bvt = bv[t];
        #pragma unroll
        for (int sl = 0; sl < 4; sl++) su[sl][t] = a[sl] + bvt;
    }
    __syncthreads();

    float xr[4], xz[4], xn[4], hr[4], hz[4], hn[4];
    #pragma unroll
    for (int sl = 0; sl < 4; sl++) {
        xr[sl] = b_ih[t]; xz[sl] = b_ih[256+t]; xn[sl] = b_ih[512+t];
        hr[sl] = b_hh[t]; hz[sl] = b_hh[256+t]; hn[sl] = b_hh[512+t];
    }
    const float* wir = w_ih + (size_t)t*256;
    const float* wiz = w_ih + (size_t)(256+t)*256;
    const float* win = w_ih + (size_t)(512+t)*256;
    const float* whr = w_hh + (size_t)t*256;
    const float* whz = w_hh + (size_t)(256+t)*256;
    const float* whn = w_hh + (size_t)(512+t)*256;

    for (int e = 0; e < 256; e += 4) {
        float4 wr4 = *(const float4*)&wir[e];
        float4 wz4 = *(const float4*)&wiz[e];
        float4 wn4 = *(const float4*)&win[e];
        float4 vr4 = *(const float4*)&whr[e];
        float4 vz4 = *(const float4*)&whz[e];
        float4 vn4 = *(const float4*)&whn[e];
        #pragma unroll
        for (int sl = 0; sl < 4; sl++) {
            float4 u4 = *(const float4*)&su[sl][e];
            float4 h4 = *(const float4*)&sh[sl][e];
            xr[sl] += wr4.x*u4.x + wr4.y*u4.y + wr4.z*u4.z + wr4.w*u4.w;
            xz[sl] += wz4.x*u4.x + wz4.y*u4.y + wz4.z*u4.z + wz4.w*u4.w;
            xn[sl] += wn4.x*u4.x + wn4.y*u4.y + wn4.z*u4.z + wn4.w*u4.w;
            hr[sl] += vr4.x*h4.x + vr4.y*h4.y + vr4.z*h4.z + vr4.w*h4.w;
            hz[sl] += vz4.x*h4.x + vz4.y*h4.y + vz4.z*h4.z + vz4.w*h4.w;
            hn[sl] += vn4.x*h4.x + vn4.y*h4.y + vn4.z*h4.z + vn4.w*h4.w;
        }
    }
    float hnew[4];
    #pragma unroll
    for (int sl = 0; sl < 4; sl++) {
        float r = sigmoidf_(xr[sl] + hr[sl]);
        float z = sigmoidf_(xz[sl] + hz[sl]);
        float nn = tanhf(xn[sl] + r*hn[sl]);
        hnew[sl] = (1.f - z)*nn + z*sh[sl][t];
    }
    __syncthreads();
    #pragma unroll
    for (int sl = 0; sl < 4; sl++) su[sl][t] = hnew[sl];
    __syncthreads();
    if (w < 4) {
        float s1 = 0.f, s2 = 0.f;
        #pragma unroll
        for (int e = 0; e < 8; e++) {
            float v = su[w][lane + e*32];
            s1 += v; s2 += v*v;
        }
        #pragma unroll
        for (int o = 16; o; o >>= 1) {
            s1 += __shfl_xor_sync(0xffffffffu, s1, o);
            s2 += __shfl_xor_sync(0xffffffffu, s2, o);
        }
        if (lane == 0) {
            float m = s1 * (1.f/256.f);
            sm[w] = m;
            sr2[w] = rsqrtf(s2 * (1.f/256.f) - m*m + EPS);
        }
    }
    __syncthreads();
    float gt = lng[t], bt = lnb[t];
    #pragma unroll
    for (int sl = 0; sl < 4; sl++)
        sa[sl][t] = (hnew[sl] - sm[sl]) * sr2[sl] * gt + bt;
    __syncthreads();

    float a1[4] = {b1[t], b1[t], b1[t], b1[t]};
    float a2[4] = {b1[256+t], b1[256+t], b1[256+t], b1[256+t]};
    const float* w1a = w1 + (size_t)t*256;
    const float* w1b = w1 + (size_t)(256+t)*256;
    for (int e = 0; e < 256; e += 4) {
        float4 wa = *(const float4*)&w1a[e];
        float4 wb = *(const float4*)&w1b[e];
        #pragma unroll
        for (int sl = 0; sl < 4; sl++) {
            float4 s4 = *(const float4*)&sa[sl][e];
            a1[sl] += wa.x*s4.x + wa.y*s4.y + wa.z*s4.z + wa.w*s4.w;
            a2[sl] += wb.x*s4.x + wb.y*s4.y + wb.z*s4.z + wb.w*s4.w;
        }
    }
    #pragma unroll
    for (int sl = 0; sl < 4; sl++) {
        sh1[sl][t]     = fmaxf(a1[sl], 0.f);
        sh1[sl][256+t] = fmaxf(a2[sl], 0.f);
    }
    __syncthreads();

    float o[4] = {b2[t], b2[t], b2[t], b2[t]};
    const float* w2r = w2 + (size_t)t*512;
    for (int e = 0; e < 512; e += 4) {
        float4 w4 = *(const float4*)&w2r[e];
        #pragma unroll
        for (int sl = 0; sl < 4; sl++) {
            float4 h4 = *(const float4*)&sh1[sl][e];
            o[sl] += w4.x*h4.x + w4.y*h4.y + w4.z*h4.z + w4.w*h4.w;
        }
    }
    float res[4];
    #pragma unroll
    for (int sl = 0; sl < 4; sl++) {
        res[sl] = hnew[sl] + o[sl];
        g_slots[(row0+sl)*256 + t] = res[sl];
        if (out_slots) out_slots[(row0+sl)*256 + t] = res[sl];
    }

    if (!do_qproj) return;

    // ======== fused qproj for next iteration (4 slots) ========
    __syncthreads();
    #pragma unroll
    for (int sl = 0; sl < 4; sl++) {
        sh[sl][t] = res[sl];
        g_U[(row0+sl)*256 + t] = 0.f;
    }
    if (t < 4) { g_cs[row0 + t] = 0.f; g_t1[row0 + t] = 0.f; }
    __syncthreads();
    if (w < 4) {
        float s1 = 0.f, s2 = 0.f;
        #pragma unroll
        for (int e = 0; e < 8; e++) {
            float v = sh[w][lane + e*32];
            s1 += v; s2 += v*v;
        }
        #pragma unroll
        for (int oo = 16; oo; oo >>= 1) {
            s1 += __shfl_xor_sync(0xffffffffu, s1, oo);
            s2 += __shfl_xor_sync(0xffffffffu, s2, oo);
        }
        if (lane == 0) {
            float m = s1 * (1.f/256.f);
            sm[w] = m;
            sr2[w] = rsqrtf(s2 * (1.f/256.f) - m*m + EPS);
        }
    }
    __syncthreads();
    float gst = lsg[t], bst = lsb[t];
    #pragma unroll
    for (int sl = 0; sl < 4; sl++)
        sa[sl][t] = (res[sl] - sm[sl]) * sr2[sl] * gst + bst;
    __syncthreads();

    {
        float q[4] = {0,0,0,0};
        const float* wr = wq + (size_t)t * 256;
        #pragma unroll 2
        for (int e = 0; e < 256; e += 4) {
            float4 w4 = *(const float4*)&wr[e];
            #pragma unroll
            for (int sl = 0; sl < 4; sl++) {
                float4 s4 = *(const float4*)&sa[sl][e];
                q[sl] += w4.x*s4.x + w4.y*s4.y + w4.z*s4.z + w4.w*s4.w;
            }
        }
        float bqt = bq[t];
        #pragma unroll
        for (int sl = 0; sl < 4; sl++) szn[sl][t] = q[sl] + bqt;
    }
    __syncthreads();

    float pgv[4] = {0,0,0,0};
    {
        const float* wr = g_wkgT + (size_t)t * 256;
        #pragma unroll 2
        for (int e = 0; e < 256; e += 4) {
            float4 w4 = *(const float4*)&wr[e];
            #pragma unroll
            for (int sl = 0; sl < 4; sl++) {
                float4 q4 = *(const float4*)&szn[sl][e];
                pgv[sl] += w4.x*q4.x + w4.y*q4.y + w4.z*q4.z + w4.w*q4.w;
            }
        }
    }
    float wkbt = g_wkb[t];
    float p2v[4];
    #pragma unroll
    for (int sl = 0; sl < 4; sl++) {
        pgv[sl] *= SCALE;
        g_p[(row0+sl)*256 + t] = pgv[sl];
        p2v[sl] = szn[sl][t] * wkbt;
    }
    #pragma unroll
    for (int sl = 0; sl < 4; sl++) {
        float v1 = pgv[sl], v2 = p2v[sl];
        #pragma unroll
        for (int oo = 16; oo; oo >>= 1) {
            v1 += __shfl_xor_sync(0xffffffffu, v1, oo);
            v2 += __shfl_xor_sync(0xffffffffu, v2, oo);
        }
        if (lane == 0) { red1[sl][w] = v1; red2[sl][w] = v2; }
    }
    __syncthreads();
    if (t < 4) {
        float a1s = 0.f, a2s = 0.f;
        #pragma unroll
        for (int i = 0; i < 8; i++) { a1s += red1[t][i]; a2s += red2[t][i]; }
        g_S1[row0 + t] = a1s;
        g_S2[row0 + t] = a2s * SCALE;
    }
}

// ---------------- K8: final attn normalize to d_out --------------------------
__global__ void k_attn_out(float* __restrict__ dst) {
    int i = blockIdx.x*blockDim.x + threadIdx.x;
    if (i < TOK*S_) {
        int s = i & 7;
        int b = i >> 15;
        dst[i] = g_attn[i] / g_cs[b*8 + s];
    }
}

// ---------------- host --------------------------------------------------------
extern "C" void kernel_launch(void* const* d_in, const int* in_sizes, int n_in,
                              void* d_out, int out_size) {
    const float* inputs     = (const float*)d_in[0];
    const float* init_noise = (const float*)d_in[1];
    const float* mu         = (const float*)d_in[2];
    const float* sigma_raw  = (const float*)d_in[3];
    const float* ln_in_g    = (const float*)d_in[4];
    const float* ln_in_b    = (const float*)d_in[5];
    const float* ln_s_g     = (const float*)d_in[6];
    const float* ln_s_b     = (const float*)d_in[7];
    const float* ln_m_g     = (const float*)d_in[8];
    const float* ln_m_b     = (const float*)d_in[9];
    const float* wq         = (const float*)d_in[10];
    const float* bq         = (const float*)d_in[11];
    const float* wk         = (const float*)d_in[12];
    const float* bk         = (const float*)d_in[13];
    const float* wv         = (const float*)d_in[14];
    const float* bv         = (const float*)d_in[15];
    const float* w_ih       = (const float*)d_in[16];
    const float* w_hh       = (const float*)d_in[17];
    const float* b_ih       = (const float*)d_in[18];
    const float* b_hh       = (const float*)d_in[19];
    const float* w1         = (const float*)d_in[20];
    const float* b1         = (const float*)d_in[21];
    const float* w2         = (const float*)d_in[22];
    const float* b2         = (const float*)d_in[23];
    float* out = (float*)d_out;

    k_prep_all<<<65, 256>>>(wk, ln_in_g, ln_in_b, bk);
    k_meanvar<<<TOK/8, 256>>>(inputs);
    k_qproj3<<<B_, 256>>>(ln_s_g, ln_s_b, wq, bq, init_noise, mu, sigma_raw);

    for (int it = 0; it < 3; ++it) {
        bool last = (it == 2);
        k_attn8<<<dim3(32, B_), 256>>>(inputs, last ? 1 : 0);
        k_gruq4<<<B_*2, 256>>>(ln_in_g, ln_in_b, wv, bv,
                               w_ih, w_hh, b_ih, b_hh, ln_m_g, ln_m_b,
                               w1, b1, w2, b2,
                               ln_s_g, ln_s_b, wq, bq,
                               last ? 0 : 1, last ? out : nullptr);
    }
    k_attn_out<<<(TOK*S_ + 255)/256, 256>>>(out + B_*S_*D_);
}

// round 16
// speedup vs baseline: 1.5248x; 1.0471x over previous
#include <cuda_runtime.h>
#include <cstdint>
#include <math.h>

#define B_   32
#define N_   4096
#define D_   256
#define S_   8
#define H_   512
#define TOK  (B_*N_)      // 131072
#define EPS  1e-5f
#define SCALE 0.0625f     // 256^-0.5

// ---------------- scratch (device globals) ----------------------------------
__device__ float g_mean[TOK];
__device__ float g_rstd[TOK];
__device__ float g_slots[B_*S_*D_];
__device__ float g_p[B_*S_*D_];      // pg = SCALE * g ∘ (q @ wk)
__device__ float g_S1[B_*S_];
__device__ float g_S2[B_*S_];
__device__ float g_attn[TOK*S_];     // last iter only
__device__ float g_cs[B_*S_];
__device__ float g_t1[B_*S_];
__device__ float g_U[B_*S_*D_];
__device__ float g_wkgT[D_*D_];      // wkgT[d][j] = ln_in_g[d]*wk[j][d]
__device__ float g_wkb[D_];          // wk @ ln_in_b + bk

__device__ __forceinline__ float sigmoidf_(float x) { return 1.f / (1.f + expf(-x)); }

// ---------------- packed f32x2 helpers ---------------------------------------
__device__ __forceinline__ unsigned long long f2pk(float lo, float hi) {
    unsigned long long r;
    asm("mov.b64 %0, {%1,%2};" : "=l"(r) : "f"(lo), "f"(hi));
    return r;
}
__device__ __forceinline__ unsigned long long fma2_(unsigned long long a,
                                                    unsigned long long b,
                                                    unsigned long long c) {
    unsigned long long d;
    asm("fma.rn.f32x2 %0, %1, %2, %3;" : "=l"(d) : "l"(a), "l"(b), "l"(c));
    return d;
}
__device__ __forceinline__ unsigned long long mul2_(unsigned long long a,
                                                    unsigned long long b) {
    unsigned long long d;
    asm("mul.rn.f32x2 %0, %1, %2;" : "=l"(d) : "l"(a), "l"(b));
    return d;
}
__device__ __forceinline__ float2 f2up(unsigned long long v) {
    float lo, hi;
    asm("mov.b64 {%0,%1}, %2;" : "=f"(lo), "=f"(hi) : "l"(v));
    return make_float2(lo, hi);
}

// ---------------- prep A: transposed g-scaled wk ------------------------------
__global__ void k_prep_t(const float* __restrict__ wk, const float* __restrict__ lng) {
    __shared__ float tile[32][33];
    int bj = blockIdx.x & 7, bd = blockIdx.x >> 3;
    int j0 = bj * 32, d0 = bd * 32;
    int tx = threadIdx.x & 31, ty = threadIdx.x >> 5;
    #pragma unroll
    for (int r = 0; r < 4; r++)
        tile[ty + 8*r][tx] = wk[(size_t)(j0 + ty + 8*r) * 256 + d0 + tx];
    __syncthreads();
    #pragma unroll
    for (int r = 0; r < 4; r++) {
        int d = d0 + ty + 8*r;
        g_wkgT[(size_t)d * 256 + j0 + tx] = lng[d] * tile[tx][ty + 8*r];
    }
}
// ---------------- prep B: wkb -------------------------------------------------
__global__ void k_prep_b(const float* __restrict__ wk, const float* __restrict__ lnb,
                         const float* __restrict__ bk) {
    int j = threadIdx.x;
    const float* wr = wk + (size_t)j * 256;
    float acc = bk[j];
    #pragma unroll 4
    for (int e = 0; e < 256; e += 4) {
        float4 w4 = *(const float4*)&wr[e];
        float4 b4 = *(const float4*)&lnb[e];
        acc += w4.x*b4.x + w4.y*b4.y + w4.z*b4.z + w4.w*b4.w;
    }
    g_wkb[j] = acc;
}

// ---------------- K1: per-token mean/rstd ------------------------------------
__global__ void k_meanvar(const float* __restrict__ x) {
    int warp = threadIdx.x >> 5, lane = threadIdx.x & 31;
    int tok = blockIdx.x * 8 + warp;
    const float4* row = (const float4*)(x + (size_t)tok * D_);
    float4 a = row[lane*2], b = row[lane*2+1];
    float s = a.x+a.y+a.z+a.w + b.x+b.y+b.z+b.w;
    float q = a.x*a.x+a.y*a.y+a.z*a.z+a.w*a.w + b.x*b.x+b.y*b.y+b.z*b.z+b.w*b.w;
    #pragma unroll
    for (int o = 16; o; o >>= 1) {
        s += __shfl_xor_sync(0xffffffffu, s, o);
        q += __shfl_xor_sync(0xffffffffu, q, o);
    }
    if (lane == 0) {
        float m = s * (1.f/256.f);
        g_mean[tok] = m;
        g_rstd[tok] = rsqrtf(q * (1.f/256.f) - m*m + EPS);
    }
}

// ---------------- K4: qproj (iteration 0 only) -------------------------------
__global__ void __launch_bounds__(256) k_qproj3(
    const float* __restrict__ g, const float* __restrict__ bln,
    const float* __restrict__ wq, const float* __restrict__ bq,
    const float* __restrict__ noise, const float* __restrict__ mu,
    const float* __restrict__ sigma_raw)
{
    __shared__ __align__(16) float sa[8][256];
    __shared__ __align__(16) float sq[8][256];
    __shared__ float sm[8], sr[8];
    __shared__ float red1[8][8], red2[8][8];
    int b = blockIdx.x, t = threadIdx.x;
    int w = t >> 5, lane = t & 31;

    float sr_ = sigma_raw[t];
    float sp = (sr_ > 20.f) ? sr_ : log1pf(expf(sr_));
    float muv = mu[t];
    #pragma unroll
    for (int s = 0; s < 8; s++) {
        float v = muv + sp * noise[(b*8+s)*256 + t];
        sa[s][t] = v;
        g_slots[(b*8+s)*256 + t] = v;
        g_U[(b*8+s)*256 + t] = 0.f;
    }
    if (t < 8) { g_cs[b*8 + t] = 0.f; g_t1[b*8 + t] = 0.f; }
    __syncthreads();

    {
        float s1 = 0.f, s2 = 0.f;
        #pragma unroll
        for (int e = 0; e < 8; e++) {
            float v = sa[w][lane + e*32];
            s1 += v; s2 += v*v;
        }
        #pragma unroll
        for (int o = 16; o; o >>= 1) {
            s1 += __shfl_xor_sync(0xffffffffu, s1, o);
            s2 += __shfl_xor_sync(0xffffffffu, s2, o);
        }
        if (lane == 0) {
            float m = s1 * (1.f/256.f);
            sm[w] = m;
            sr[w] = rsqrtf(s2 * (1.f/256.f) - m*m + EPS);
        }
    }
    __syncthreads();
    float gt = g[t], bt = bln[t];
    #pragma unroll
    for (int s = 0; s < 8; s++)
        sa[s][t] = (sa[s][t] - sm[s]) * sr[s] * gt + bt;
    __syncthreads();

    {
        float acc[8] = {0,0,0,0,0,0,0,0};
        const float* wr = wq + (size_t)t * 256;
        #pragma unroll 2
        for (int e = 0; e < 256; e += 4) {
            float4 w4 = *(const float4*)&wr[e];
            #pragma unroll
            for (int s = 0; s < 8; s++) {
                float4 a4 = *(const float4*)&sa[s][e];
                acc[s] += w4.x*a4.x + w4.y*a4.y + w4.z*a4.z + w4.w*a4.w;
            }
        }
        float bqt = bq[t];
        #pragma unroll
        for (int s = 0; s < 8; s++) sq[s][t] = acc[s] + bqt;
    }
    __syncthreads();

    float pgv[8] = {0,0,0,0,0,0,0,0};
    {
        const float* wr = g_wkgT + (size_t)t * 256;
        #pragma unroll 2
        for (int e = 0; e < 256; e += 4) {
            float4 w4 = *(const float4*)&wr[e];
            #pragma unroll
            for (int s = 0; s < 8; s++) {
                float4 q4 = *(const float4*)&sq[s][e];
                pgv[s] += w4.x*q4.x + w4.y*q4.y + w4.z*q4.z + w4.w*q4.w;
            }
        }
    }
    float wkbt = g_wkb[t];
    float p2[8];
    #pragma unroll
    for (int s = 0; s < 8; s++) {
        pgv[s] *= SCALE;
        g_p[(b*8+s)*256 + t] = pgv[s];
        p2[s] = sq[s][t] * wkbt;
    }
    #pragma unroll
    for (int s = 0; s < 8; s++) {
        float v1 = pgv[s], v2 = p2[s];
        #pragma unroll
        for (int o = 16; o; o >>= 1) {
            v1 += __shfl_xor_sync(0xffffffffu, v1, o);
            v2 += __shfl_xor_sync(0xffffffffu, v2, o);
        }
        if (lane == 0) { red1[s][w] = v1; red2[s][w] = v2; }
    }
    __syncthreads();
    if (t < 8) {
        float a1 = 0.f, a2 = 0.f;
        #pragma unroll
        for (int i = 0; i < 8; i++) { a1 += red1[t][i]; a2 += red2[t][i]; }
        g_S1[b*8 + t] = a1;
        g_S2[b*8 + t] = a2 * SCALE;
    }
}

// ---------------- K5: fused attn (packed f32x2 FMA, 2-token interleaved) ----
__global__ void __launch_bounds__(256, 2) k_attn8(const float* __restrict__ x,
                                                  int store_attn) {
    __shared__ __align__(16) float sA[32][8];
    int b = blockIdx.y, chunk = blockIdx.x;
    int t = threadIdx.x;
    int wid = t >> 5, lane = t & 31;
    int slot = (lane >> 2) & 7;

    unsigned long long pgp[8][4];
    {
        const float* pb = g_p + b*S_*D_;
        #pragma unroll
        for (int s = 0; s < 8; s++) {
            float4 a = *(const float4*)&pb[s*256 + lane*8];
            float4 c = *(const float4*)&pb[s*256 + lane*8 + 4];
            pgp[s][0] = f2pk(a.x, a.y);
            pgp[s][1] = f2pk(a.z, a.w);
            pgp[s][2] = f2pk(c.x, c.y);
            pgp[s][3] = f2pk(c.z, c.w);
        }
    }
    float S1l = g_S1[b*8 + slot];
    float S2l = g_S2[b*8 + slot];

    unsigned long long u2[4];
    #pragma unroll
    for (int j = 0; j < 4; j++) u2[j] = f2pk(0.f, 0.f);
    float csA = 0.f, t1A = 0.f;
    int base_tok = b*N_ + chunk*128;

    for (int sub = 0; sub < 4; sub++) {
        int sub0 = sub * 32;
        #pragma unroll
        for (int i = 0; i < 4; i += 2) {
            int locA = sub0 + wid*4 + i;
            int nA = base_tok + locA;
            int nB = nA + 1;
            const float* xrA = x + (size_t)nA*256 + lane*8;
            const float* xrB = x + (size_t)nB*256 + lane*8;
            float4 xaA = *(const float4*)xrA;
            float4 xbA = *(const float4*)(xrA + 4);
            float4 xaB = *(const float4*)xrB;
            float4 xbB = *(const float4*)(xrB + 4);
            unsigned long long xpA[4], xpB[4];
            xpA[0] = f2pk(xaA.x, xaA.y); xpA[1] = f2pk(xaA.z, xaA.w);
            xpA[2] = f2pk(xbA.x, xbA.y); xpA[3] = f2pk(xbA.z, xbA.w);
            xpB[0] = f2pk(xaB.x, xaB.y); xpB[1] = f2pk(xaB.z, xaB.w);
            xpB[2] = f2pk(xbB.x, xbB.y); xpB[3] = f2pk(xbB.z, xbB.w);

            float dA[8], dB[8];
            #pragma unroll
            for (int s = 0; s < 8; s++) {
                unsigned long long aA = mul2_(xpA[0], pgp[s][0]);
                unsigned long long aB = mul2_(xpB[0], pgp[s][0]);
                aA = fma2_(xpA[1], pgp[s][1], aA);
                aB = fma2_(xpB[1], pgp[s][1], aB);
                aA = fma2_(xpA[2], pgp[s][2], aA);
                aB = fma2_(xpB[2], pgp[s][2], aB);
                aA = fma2_(xpA[3], pgp[s][3], aA);
                aB = fma2_(xpB[3], pgp[s][3], aB);
                float2 fA = f2up(aA), fB = f2up(aB);
                dA[s] = fA.x + fA.y;
                dB[s] = fB.x + fB.y;
            }
            bool h16 = (lane & 16) != 0;
            float eA0, eA1, eA2, eA3, eB0, eB1, eB2, eB3;
            {
                float rA0 = __shfl_xor_sync(0xffffffffu, dA[0], 16);
                float rB0 = __shfl_xor_sync(0xffffffffu, dB[0], 16);
                float rA1 = __shfl_xor_sync(0xffffffffu, dA[1], 16);
                float rB1 = __shfl_xor_sync(0xffffffffu, dB[1], 16);
                float rA2 = __shfl_xor_sync(0xffffffffu, dA[2], 16);
                float rB2 = __shfl_xor_sync(0xffffffffu, dB[2], 16);
                float rA3 = __shfl_xor_sync(0xffffffffu, dA[3], 16);
                float rB3 = __shfl_xor_sync(0xffffffffu, dB[3], 16);
                float rA4 = __shfl_xor_sync(0xffffffffu, dA[4], 16);
                float rB4 = __shfl_xor_sync(0xffffffffu, dB[4], 16);
                float rA5 = __shfl_xor_sync(0xffffffffu, dA[5], 16);
                float rB5 = __shfl_xor_sync(0xffffffffu, dB[5], 16);
                float rA6 = __shfl_xor_sync(0xffffffffu, dA[6], 16);
                float rB6 = __shfl_xor_sync(0xffffffffu, dB[6], 16);
                float rA7 = __shfl_xor_sync(0xffffffffu, dA[7], 16);
                float rB7 = __shfl_xor_sync(0xffffffffu, dB[7], 16);
                eA0 = h16 ? (dA[4]+rA4) : (dA[0]+rA0);
                eA1 = h16 ? (dA[5]+rA5) : (dA[1]+rA1);
                eA2 = h16 ? (dA[6]+rA6) : (dA[2]+rA2);
                eA3 = h16 ? (dA[7]+rA7) : (dA[3]+rA3);
                eB0 = h16 ? (dB[4]+rB4) : (dB[0]+rB0);
                eB1 = h16 ? (dB[5]+rB5) : (dB[1]+rB1);
                eB2 = h16 ? (dB[6]+rB6) : (dB[2]+rB2);
                eB3 = h16 ? (dB[7]+rB7) : (dB[3]+rB3);
            }
            bool h8 = (lane & 8) != 0;
            float fA0, fA1, fB0, fB1;
            {
                float rA0 = __shfl_xor_sync(0xffffffffu, eA0, 8);
                float rB0 = __shfl_xor_sync(0xffffffffu, eB0, 8);
                float rA1 = __shfl_xor_sync(0xffffffffu, eA1, 8);
                float rB1 = __shfl_xor_sync(0xffffffffu, eB1, 8);
                float rA2 = __shfl_xor_sync(0xffffffffu, eA2, 8);
                float rB2 = __shfl_xor_sync(0xffffffffu, eB2, 8);
                float rA3 = __shfl_xor_sync(0xffffffffu, eA3, 8);
                float rB3 = __shfl_xor_sync(0xffffffffu, eB3, 8);
                fA0 = h8 ? (eA2+rA2) : (eA0+rA0);
                fA1 = h8 ? (eA3+rA3) : (eA1+rA1);
                fB0 = h8 ? (eB2+rB2) : (eB0+rB0);
                fB1 = h8 ? (eB3+rB3) : (eB1+rB1);
            }
            bool h4 = (lane & 4) != 0;
            float vA, vB;
            {
                float rA0 = __shfl_xor_sync(0xffffffffu, fA0, 4);
                float rB0 = __shfl_xor_sync(0xffffffffu, fB0, 4);
                float rA1 = __shfl_xor_sync(0xffffffffu, fA1, 4);
                float rB1 = __shfl_xor_sync(0xffffffffu, fB1, 4);
                vA = h4 ? (fA1+rA1) : (fA0+rA0);
                vB = h4 ? (fB1+rB1) : (fB0+rB0);
            }
            vA += __shfl_xor_sync(0xffffffffu, vA, 2);
            vB += __shfl_xor_sync(0xffffffffu, vB, 2);
            vA += __shfl_xor_sync(0xffffffffu, vA, 1);
            vB += __shfl_xor_sync(0xffffffffu, vB, 1);

            float rA = g_rstd[nA], mA = g_mean[nA];
            float rB = g_rstd[nB], mB = g_mean[nB];
            float rmA = rA * mA, rmB = rB * mB;
            float lgA = rA*vA - rmA*S1l + S2l;
            float lgB = rB*vB - rmB*S1l + S2l;
            float eA = expf(lgA);
            float eB = expf(lgB);
            float sumA = eA, sumB = eB;
            sumA += __shfl_xor_sync(0xffffffffu, sumA, 4);
            sumB += __shfl_xor_sync(0xffffffffu, sumB, 4);
            sumA += __shfl_xor_sync(0xffffffffu, sumA, 8);
            sumB += __shfl_xor_sync(0xffffffffu, sumB, 8);
            sumA += __shfl_xor_sync(0xffffffffu, sumA, 16);
            sumB += __shfl_xor_sync(0xffffffffu, sumB, 16);
            float aA = eA / sumA + 1e-8f;
            float aB = eB / sumB + 1e-8f;
            csA += aA + aB;
            t1A += aA * rmA + aB * rmB;
            if ((lane & 3) == 0) {
                sA[locA - sub0][slot]     = aA * rA;
                sA[locA - sub0 + 1][slot] = aB * rB;
                if (store_attn) {
                    g_attn[(size_t)nA*8 + slot] = aA;
                    g_attn[(size_t)nB*8 + slot] = aB;
                }
            }
        }
        __syncthreads();
        const float* xcol = x + (size_t)(base_tok + sub0)*256 + t;
        #pragma unroll 8
        for (int i = 0; i < 32; i++) {
            float xv = xcol[(size_t)i*256];
            unsigned long long xvp = f2pk(xv, xv);
            const unsigned long long* sp = (const unsigned long long*)&sA[i][0];
            u2[0] = fma2_(sp[0], xvp, u2[0]);
            u2[1] = fma2_(sp[1], xvp, u2[1]);
            u2[2] = fma2_(sp[2], xvp, u2[2]);
            u2[3] = fma2_(sp[3], xvp, u2[3]);
        }
        __syncthreads();
    }

    #pragma unroll
    for (int j = 0; j < 4; j++) {
        float2 uv = f2up(u2[j]);
        atomicAdd(&g_U[(b*8 + 2*j)    *256 + t], uv.x);
        atomicAdd(&g_U[(b*8 + 2*j + 1)*256 + t], uv.y);
    }
    if ((lane & 3) == 0) {
        atomicAdd(&g_cs[b*8 + slot], csA);
        atomicAdd(&g_t1[b*8 + slot], t1A);
    }
}

// ---------------- K7: GRU+LN+MLP+qproj, 512 threads, split-K matvecs ---------
// grid 128 CTAs, 2 slots per CTA. Each output computed by a thread PAIR over
// half the reduction; combine via shfl_xor(.,1).
__global__ void __launch_bounds__(512) k_gruq2(
    const float* __restrict__ lng_in, const float* __restrict__ lnb_in,
    const float* __restrict__ wv,   const float* __restrict__ bv,
    const float* __restrict__ w_ih, const float* __restrict__ w_hh,
    const float* __restrict__ b_ih, const float* __restrict__ b_hh,
    const float* __restrict__ lng,  const float* __restrict__ lnb,
    const float* __restrict__ w1,   const float* __restrict__ b1,
    const float* __restrict__ w2,   const float* __restrict__ b2,
    const float* __restrict__ lsg,  const float* __restrict__ lsb,
    const float* __restrict__ wq,   const float* __restrict__ bq,
    int do_qproj, float* __restrict__ out_slots)
{
    __shared__ __align__(16) float szn[2][256];   // zn, later hnew
    __shared__ __align__(16) float su[2][256];    // updates, later q
    __shared__ __align__(16) float sh[2][256];    // slots, later res
    __shared__ __align__(16) float sa[2][256];    // LN outputs
    __shared__ __align__(16) float sh1[2][512];
    __shared__ float sm[2], sr2[2];
    __shared__ float red1[2][16], red2[2][16];

    int b = blockIdx.x >> 2;
    int p = blockIdx.x & 3;
    int row0 = b*8 + p*2;
    int t = threadIdx.x;           // 0..511
    int out = t >> 1, half = t & 1;
    int eb = half * 128;
    int w = t >> 5, lane = t & 31;

    {   // load zn + slots (512 threads cover 2x256)
        int sl = t >> 8, idx = t & 255;
        int row = row0 + sl;
        float csv = g_cs[row], t1v = g_t1[row];
        float Ut = g_U[row*256 + idx];
        szn[sl][idx] = lng_in[idx] * (Ut - t1v) / csv + lnb_in[idx];
        sh[sl][idx] = g_slots[row*256 + idx];
    }
    __syncthreads();

    // ---- su = zn @ wv^T + bv (split-K) ----
    {
        float a0 = 0.f, a1 = 0.f;
        const float* wr = wv + (size_t)out * 256 + eb;
        #pragma unroll 4
        for (int e = 0; e < 128; e += 4) {
            float4 w4 = *(const float4*)&wr[e];
            float4 z0 = *(const float4*)&szn[0][eb + e];
            float4 z1 = *(const float4*)&szn[1][eb + e];
            a0 += w4.x*z0.x + w4.y*z0.y + w4.z*z0.z + w4.w*z0.w;
            a1 += w4.x*z1.x + w4.y*z1.y + w4.z*z1.z + w4.w*z1.w;
        }
        a0 += __shfl_xor_sync(0xffffffffu, a0, 1);
        a1 += __shfl_xor_sync(0xffffffffu, a1, 1);
        if (!half) {
            float bvt = bv[out];
            su[0][out] = a0 + bvt;
            su[1][out] = a1 + bvt;
        }
    }
    __syncthreads();

    // ---- GRU gates (6 matvecs, split-K) ----
    float hnew0, hnew1;
    {
        float xr0=0,xz0=0,xn0=0,hr0=0,hz0=0,hn0=0;
        float xr1=0,xz1=0,xn1=0,hr1=0,hz1=0,hn1=0;
        const float* wir = w_ih + (size_t)out*256 + eb;
        const float* wiz = w_ih + (size_t)(256+out)*256 + eb;
        const float* win = w_ih + (size_t)(512+out)*256 + eb;
        const float* whr = w_hh + (size_t)out*256 + eb;
        const float* whz = w_hh + (size_t)(256+out)*256 + eb;
        const float* whn = w_hh + (size_t)(512+out)*256 + eb;
        #pragma unroll 2
        for (int e = 0; e < 128; e += 4) {
            float4 u0 = *(const float4*)&su[0][eb + e];
            float4 u1 = *(const float4*)&su[1][eb + e];
            float4 h0 = *(const float4*)&sh[0][eb + e];
            float4 h1 = *(const float4*)&sh[1][eb + e];
            float4 ww;
            ww = *(const float4*)&wir[e];
            xr0 += ww.x*u0.x + ww.y*u0.y + ww.z*u0.z + ww.w*u0.w;
            xr1 += ww.x*u1.x + ww.y*u1.y + ww.z*u1.z + ww.w*u1.w;
            ww = *(const float4*)&wiz[e];
            xz0 += ww.x*u0.x + ww.y*u0.y + ww.z*u0.z + ww.w*u0.w;
            xz1 += ww.x*u1.x + ww.y*u1.y + ww.z*u1.z + ww.w*u1.w;
            ww = *(const float4*)&win[e];
            xn0 += ww.x*u0.x + ww.y*u0.y + ww.z*u0.z + ww.w*u0.w;
            xn1 += ww.x*u1.x + ww.y*u1.y + ww.z*u1.z + ww.w*u1.w;
            ww = *(const float4*)&whr[e];
            hr0 += ww.x*h0.x + ww.y*h0.y + ww.z*h0.z + ww.w*h0.w;
            hr1 += ww.x*h1.x + ww.y*h1.y + ww.z*h1.z + ww.w*h1.w;
            ww = *(const float4*)&whz[e];
            hz0 += ww.x*h0.x + ww.y*h0.y + ww.z*h0.z + ww.w*h0.w;
            hz1 += ww.x*h1.x + ww.y*h1.y + ww.z*h1.z + ww.w*h1.w;
            ww = *(const float4*)&whn[e];
            hn0 += ww.x*h0.x + ww.y*h0.y + ww.z*h0.z + ww.w*h0.w;
            hn1 += ww.x*h1.x + ww.y*h1.y + ww.z*h1.z + ww.w*h1.w;
        }
        xr0 += __shfl_xor_sync(0xffffffffu, xr0, 1);
        xz0 += __shfl_xor_sync(0xffffffffu, xz0, 1);
        xn0 += __shfl_xor_sync(0xffffffffu, xn0, 1);
        hr0 += __shfl_xor_sync(0xffffffffu, hr0, 1);
        hz0 += __shfl_xor_sync(0xffffffffu, hz0, 1);
        hn0 += __shfl_xor_sync(0xffffffffu, hn0, 1);
        xr1 += __shfl_xor_sync(0xffffffffu, xr1, 1);
        xz1 += __shfl_xor_sync(0xffffffffu, xz1, 1);
        xn1 += __shfl_xor_sync(0xffffffffu, xn1, 1);
        hr1 += __shfl_xor_sync(0xffffffffu, hr1, 1);
        hz1 += __shfl_xor_sync(0xffffffffu, hz1, 1);
        hn1 += __shfl_xor_sync(0xffffffffu, hn1, 1);
        float bir = b_ih[out], biz = b_ih[256+out], bin_ = b_ih[512+out];
        float bhr = b_hh[out], bhz = b_hh[256+out], bhn = b_hh[512+out];
        float hp0 = sh[0][out], hp1 = sh[1][out];
        {
            float r = sigmoidf_((xr0+bir) + (hr0+bhr));
            float z = sigmoidf_((xz0+biz) + (hz0+bhz));
            float nn = tanhf((xn0+bin_) + r*(hn0+bhn));
            hnew0 = (1.f - z)*nn + z*hp0;
        }
        {
            float r = sigmoidf_((xr1+bir) + (hr1+bhr));
            float z = sigmoidf_((xz1+biz) + (hz1+bhz));
            float nn = tanhf((xn1+bin_) + r*(hn1+bhn));
            hnew1 = (1.f - z)*nn + z*hp1;
        }
    }
    __syncthreads();
    if (!half) { szn[0][out] = hnew0; szn[1][out] = hnew1; }
    __syncthreads();

    // ---- LN_m stats ----
    if (w < 2) {
        float s1 = 0.f, s2 = 0.f;
        #pragma unroll
        for (int e = 0; e < 8; e++) {
            float v = szn[w][lane + e*32];
            s1 += v; s2 += v*v;
        }
        #pragma unroll
        for (int o = 16; o; o >>= 1) {
            s1 += __shfl_xor_sync(0xffffffffu, s1, o);
            s2 += __shfl_xor_sync(0xffffffffu, s2, o);
        }
        if (lane == 0) {
            float m = s1 * (1.f/256.f);
            sm[w] = m;
            sr2[w] = rsqrtf(s2 * (1.f/256.f) - m*m + EPS);
        }
    }
    __syncthreads();
    {
        int sl = t >> 8, idx = t & 255;
        sa[sl][idx] = (szn[sl][idx] - sm[sl]) * sr2[sl] * lng[idx] + lnb[idx];
    }
    __syncthreads();

    // ---- MLP1: 512 outputs, thread t -> row t (full 256 reduction) ----
    {
        float a0 = b1[t], a1 = b1[t];
        const float* wr = w1 + (size_t)t * 256;
        #pragma unroll 2
        for (int e = 0; e < 256; e += 4) {
            float4 w4 = *(const float4*)&wr[e];
            float4 s0 = *(const float4*)&sa[0][e];
            float4 s1v = *(const float4*)&sa[1][e];
            a0 += w4.x*s0.x + w4.y*s0.y + w4.z*s0.z + w4.w*s0.w;
            a1 += w4.x*s1v.x + w4.y*s1v.y + w4.z*s1v.z + w4.w*s1v.w;
        }
        sh1[0][t] = fmaxf(a0, 0.f);
        sh1[1][t] = fmaxf(a1, 0.f);
    }
    __syncthreads();

    // ---- MLP2: split-K over 512 inputs ----
    float res0, res1;
    {
        float o0 = 0.f, o1 = 0.f;
        const float* wr = w2 + (size_t)out * 512 + half*256;
        int hb = half * 256;
        #pragma unroll 4
        for (int e = 0; e < 256; e += 4) {
            float4 w4 = *(const float4*)&wr[e];
            float4 h0 = *(const float4*)&sh1[0][hb + e];
            float4 h1 = *(const float4*)&sh1[1][hb + e];
            o0 += w4.x*h0.x + w4.y*h0.y + w4.z*h0.z + w4.w*h0.w;
            o1 += w4.x*h1.x + w4.y*h1.y + w4.z*h1.z + w4.w*h1.w;
        }
        o0 += __shfl_xor_sync(0xffffffffu, o0, 1);
        o1 += __shfl_xor_sync(0xffffffffu, o1, 1);
        float b2t = b2[out];
        res0 = szn[0][out] + o0 + b2t;
        res1 = szn[1][out] + o1 + b2t;
        if (!half) {
            g_slots[(row0+0)*256 + out] = res0;
            g_slots[(row0+1)*256 + out] = res1;
            if (out_slots) {
                out_slots[(row0+0)*256 + out] = res0;
                out_slots[(row0+1)*256 + out] = res1;
            }
        }
    }
    if (!do_qproj) return;

    __syncthreads();
    if (!half) { sh[0][out] = res0; sh[1][out] = res1; }
    {   // zero accumulators for next iter
        int sl = t >> 8, idx = t & 255;
        g_U[(row0+sl)*256 + idx] = 0.f;
    }
    if (t < 2) { g_cs[row0 + t] = 0.f; g_t1[row0 + t] = 0.f; }
    __syncthreads();

    // LN_s stats on res
    if (w < 2) {
        float s1 = 0.f, s2 = 0.f;
        #pragma unroll
        for (int e = 0; e < 8; e++) {
            float v = sh[w][lane + e*32];
            s1 += v; s2 += v*v;
        }
        #pragma unroll
        for (int o = 16; o; o >>= 1) {
            s1 += __shfl_xor_sync(0xffffffffu, s1, o);
            s2 += __shfl_xor_sync(0xffffffffu, s2, o);
        }
        if (lane == 0) {
            float m = s1 * (1.f/256.f);
            sm[w] = m;
            sr2[w] = rsqrtf(s2 * (1.f/256.f) - m*m + EPS);
        }
    }
    __syncthreads();
    {
        int sl = t >> 8, idx = t & 255;
        sa[sl][idx] = (sh[sl][idx] - sm[sl]) * sr2[sl] * lsg[idx] + lsb[idx];
    }
    __syncthreads();

    // q = LN_s(res) @ wq^T + bq  (split-K)
    {
        float q0 = 0.f, q1 = 0.f;
        const float* wr = wq + (size_t)out * 256 + eb;
        #pragma unroll 4
        for (int e = 0; e < 128; e += 4) {
            float4 w4 = *(const float4*)&wr[e];
            float4 s0 = *(const float4*)&sa[0][eb + e];
            float4 s1v = *(const float4*)&sa[1][eb + e];
            q0 += w4.x*s0.x + w4.y*s0.y + w4.z*s0.z + w4.w*s0.w;
            q1 += w4.x*s1v.x + w4.y*s1v.y + w4.z*s1v.z + w4.w*s1v.w;
        }
        q0 += __shfl_xor_sync(0xffffffffu, q0, 1);
        q1 += __shfl_xor_sync(0xffffffffu, q1, 1);
        if (!half) {
            float bqt = bq[out];
            su[0][out] = q0 + bqt;
            su[1][out] = q1 + bqt;
        }
    }
    __syncthreads();

    // pg = SCALE * q @ wkgT^T (split-K); S1/S2
    float pg0 = 0.f, pg1 = 0.f;
    {
        const float* wr = g_wkgT + (size_t)out * 256 + eb;
        #pragma unroll 4
        for (int e = 0; e < 128; e += 4) {
            float4 w4 = *(const float4*)&wr[e];
            float4 q0 = *(const float4*)&su[0][eb + e];
            float4 q1 = *(const float4*)&su[1][eb + e];
            pg0 += w4.x*q0.x + w4.y*q0.y + w4.z*q0.z + w4.w*q0.w;
            pg1 += w4.x*q1.x + w4.y*q1.y + w4.z*q1.z + w4.w*q1.w;
        }
        pg0 += __shfl_xor_sync(0xffffffffu, pg0, 1);
        pg1 += __shfl_xor_sync(0xffffffffu, pg1, 1);
        pg0 *= SCALE; pg1 *= SCALE;
        if (!half) {
            g_p[(row0+0)*256 + out] = pg0;
            g_p[(row0+1)*256 + out] = pg1;
        }
    }
    // pair threads hold identical pg; full-warp sum double-counts -> *0.5
    float wkbt = g_wkb[out];
    float p20 = su[0][out] * wkbt;
    float p21 = su[1][out] * wkbt;
    {
        float v0 = pg0, v1 = pg1, v2 = p20, v3 = p21;
        #pragma unroll
        for (int o = 16; o; o >>= 1) {
            v0 += __shfl_xor_sync(0xffffffffu, v0, o);
            v1 += __shfl_xor_sync(0xffffffffu, v1, o);
            v2 += __shfl_xor_sync(0xffffffffu, v2, o);
            v3 += __shfl_xor_sync(0xffffffffu, v3, o);
        }
        if (lane == 0) {
            red1[0][w] = v0; red1[1][w] = v1;
            red2[0][w] = v2; red2[1][w] = v3;
        }
    }
    __syncthreads();
    if (t < 2) {
        float a1s = 0.f, a2s = 0.f;
        #pragma unroll
        for (int i = 0; i < 16; i++) { a1s += red1[t][i]; a2s += red2[t][i]; }
        g_S1[row0 + t] = a1s * 0.5f;
        g_S2[row0 + t] = a2s * 0.5f * SCALE;
    }
}

// ---------------- K8: final attn normalize to d_out --------------------------
__global__ void k_attn_out(float* __restrict__ dst) {
    int i = blockIdx.x*blockDim.x + threadIdx.x;
    if (i < TOK*S_) {
        int s = i & 7;
        int b = i >> 15;
        dst[i] = g_attn[i] / g_cs[b*8 + s];
    }
}

// ---------------- host --------------------------------------------------------
extern "C" void kernel_launch(void* const* d_in, const int* in_sizes, int n_in,
                              void* d_out, int out_size) {
    const float* inputs     = (const float*)d_in[0];
    const float* init_noise = (const float*)d_in[1];
    const float* mu         = (const float*)d_in[2];
    const float* sigma_raw  = (const float*)d_in[3];
    const float* ln_in_g    = (const float*)d_in[4];
    const float* ln_in_b    = (const float*)d_in[5];
    const float* ln_s_g     = (const float*)d_in[6];
    const float* ln_s_b     = (const float*)d_in[7];
    const float* ln_m_g     = (const float*)d_in[8];
    const float* ln_m_b     = (const float*)d_in[9];
    const float* wq         = (const float*)d_in[10];
    const float* bq         = (const float*)d_in[11];
    const float* wk         = (const float*)d_in[12];
    const float* bk         = (const float*)d_in[13];
    const float* wv         = (const float*)d_in[14];
    const float* bv         = (const float*)d_in[15];
    const float* w_ih       = (const float*)d_in[16];
    const float* w_hh       = (const float*)d_in[17];
    const float* b_ih       = (const float*)d_in[18];
    const float* b_hh       = (const float*)d_in[19];
    const float* w1         = (const float*)d_in[20];
    const float* b1         = (const float*)d_in[21];
    const float* w2         = (const float*)d_in[22];
    const float* b2         = (const float*)d_in[23];
    float* out = (float*)d_out;

    // launch order arranged so ncu (-s 5 -c 1) profiles k_gruq2 (6th launch)
    k_prep_t<<<64, 256>>>(wk, ln_in_g);
    k_prep_b<<<1, 256>>>(wk, ln_in_b, bk);
    k_meanvar<<<TOK/8, 256>>>(inputs);
    k_qproj3<<<B_, 256>>>(ln_s_g, ln_s_b, wq, bq, init_noise, mu, sigma_raw);

    for (int it = 0; it < 3; ++it) {
        bool last = (it == 2);
        k_attn8<<<dim3(32, B_), 256>>>(inputs, last ? 1 : 0);
        k_gruq2<<<B_*4, 512>>>(ln_in_g, ln_in_b, wv, bv,
                               w_ih, w_hh, b_ih, b_hh, ln_m_g, ln_m_b,
                               w1, b1, w2, b2,
                               ln_s_g, ln_s_b, wq, bq,
                               last ? 0 : 1, last ? out : nullptr);
    }
    k_attn_out<<<(TOK*S_ + 255)/256, 256>>>(out + B_*S_*D_);
}